// round 9
// baseline (speedup 1.0000x reference)
#include <cuda_runtime.h>
#include <cuda_bf16.h>
#include <cstdint>
#include <math.h>

// ---------------------------------------------------------------------------
// Problem: x[4,2048,1024] f32; W_qkv[1024,3072]; W_o[1024,1024]; out[4,2048,1024]
//   1) split x -> A' bf16 [8192, 3072]  (hi | lo | hi along K)
//   2) split/transpose W_qkv -> B' bf16 [3072, 3072] (hi ; hi ; lo)
//   3) HMMA bf16 GEMM (BK=64, 3-stage pipe) -> g_qkv
//   4) tf32 mma attention (R4 inner loops) -> coalesced fused split epilogue
//   5) split/transpose W_o -> B'
//   6) HMMA bf16 GEMM -> out
// ---------------------------------------------------------------------------
#define BB 4
#define NN 2048
#define DD 1024
#define HH 16
#define EE 64
#define MTOT (BB * NN)   // 8192
#define KP   3072
#define SA   72          // gemm smem row stride in bf16 (64 data + 8 pad)
#define NSTAGE 48        // KP / 64
#define PIPE 3

__device__ float         g_qkv[MTOT * 3 * DD];
__device__ __nv_bfloat16 g_A[MTOT * KP];
__device__ __nv_bfloat16 g_B[3 * DD * KP];

// ===========================================================================
__device__ __forceinline__ uint32_t smem_u32(const void* p) {
    uint32_t a;
    asm("{ .reg .u64 t; cvta.to.shared.u64 t, %1; cvt.u32.u64 %0, t; }"
        : "=r"(a) : "l"(p));
    return a;
}
__device__ __forceinline__ void cp_async16(uint32_t dst, const void* src) {
    asm volatile("cp.async.cg.shared.global [%0], [%1], 16;"
                 :: "r"(dst), "l"(src) : "memory");
}
__device__ __forceinline__ void ldsm_x4(uint32_t* r, uint32_t addr) {
    asm volatile("ldmatrix.sync.aligned.m8n8.x4.shared.b16 {%0,%1,%2,%3}, [%4];"
                 : "=r"(r[0]), "=r"(r[1]), "=r"(r[2]), "=r"(r[3]) : "r"(addr));
}
__device__ __forceinline__ void mma_bf16(float* d, const uint32_t* a, const uint32_t* b) {
    asm volatile(
        "mma.sync.aligned.m16n8k16.row.col.f32.bf16.bf16.f32 "
        "{%0,%1,%2,%3}, {%4,%5,%6,%7}, {%8,%9}, {%0,%1,%2,%3};"
        : "+f"(d[0]), "+f"(d[1]), "+f"(d[2]), "+f"(d[3])
        : "r"(a[0]), "r"(a[1]), "r"(a[2]), "r"(a[3]), "r"(b[0]), "r"(b[1]));
}
__device__ __forceinline__ float tf32r(float x) {
    asm("cvt.rna.tf32.f32 %0, %0;" : "+f"(x));
    return x;
}
__device__ __forceinline__ void mma_tf32(float* d, const float* a, float b0f, float b1f) {
    uint32_t a0 = __float_as_uint(a[0]), a1 = __float_as_uint(a[1]);
    uint32_t a2 = __float_as_uint(a[2]), a3 = __float_as_uint(a[3]);
    uint32_t b0 = __float_as_uint(b0f), b1 = __float_as_uint(b1f);
    asm volatile(
        "mma.sync.aligned.m16n8k8.row.col.f32.tf32.tf32.f32 "
        "{%0,%1,%2,%3}, {%4,%5,%6,%7}, {%8,%9}, {%0,%1,%2,%3};"
        : "+f"(d[0]), "+f"(d[1]), "+f"(d[2]), "+f"(d[3])
        : "r"(a0), "r"(a1), "r"(a2), "r"(a3), "r"(b0), "r"(b1));
}
__device__ __forceinline__ uint32_t pack_bf16(__nv_bfloat16 a, __nv_bfloat16 b) {
    __nv_bfloat162 p; p.x = a; p.y = b;
    return *reinterpret_cast<uint32_t*>(&p);
}

// ===========================================================================
// HMMA GEMM: C[M,Nn] f32 = A[M,KP] bf16 @ B[Nn,KP]^T bf16
// CTA 128x128, 8 warps of 64x32, BK=64, 3-stage cp.async ring.
// ===========================================================================
#define BUFB (128 * SA * 2)                 // 18432 B per matrix per stage
#define SMEM_GEMM (PIPE * 2 * BUFB)         // 110592

__global__ __launch_bounds__(256, 2)
void gemm_hmma(const __nv_bfloat16* __restrict__ A,
               const __nv_bfloat16* __restrict__ B,
               float* __restrict__ C, int M, int Nn) {
    extern __shared__ __nv_bfloat16 smbf[];
    const int tid  = threadIdx.x;
    const int wid  = tid >> 5;
    const int lane = tid & 31;
    const int m0 = blockIdx.y * 128;
    const int n0 = blockIdx.x * 128;
    const int wm = (wid >> 2) * 64;
    const int wn = (wid & 3) * 32;

    const uint32_t sbase = smem_u32(smbf);
    const uint32_t aoff0 = sbase;
    const uint32_t boff0 = sbase + PIPE * BUFB;

    const __nv_bfloat16* Ag = A + (size_t)m0 * KP;
    const __nv_bfloat16* Bg = B + (size_t)n0 * KP;

    // global->smem: thread -> row tid/2, four 16B chunks (half of 64 cols)
    const int lr  = tid >> 1;
    const int lcb = (tid & 1) * 4;

    auto load_stage = [&](int s) {
        const int buf = s % PIPE;
        const uint32_t ab = aoff0 + buf * BUFB;
        const uint32_t bb = boff0 + buf * BUFB;
        const int k0 = s * 64;
        const __nv_bfloat16* arow = Ag + (size_t)lr * KP + k0;
        const __nv_bfloat16* brow = Bg + (size_t)lr * KP + k0;
#pragma unroll
        for (int c = 0; c < 4; c++) {
            const int kc = lcb + c;
            const uint32_t doff = (uint32_t)(lr * SA + kc * 8) * 2;
            cp_async16(ab + doff, arow + kc * 8);
            cp_async16(bb + doff, brow + kc * 8);
        }
        asm volatile("cp.async.commit_group;" ::: "memory");
    };

    float acc[4][4][4];
#pragma unroll
    for (int i = 0; i < 4; i++)
#pragma unroll
        for (int j = 0; j < 4; j++)
#pragma unroll
            for (int k = 0; k < 4; k++) acc[i][j][k] = 0.0f;

    const int arow  = wm + (lane & 15);
    const int akoff = (lane >> 4) * 8;
    const int brow  = wn + (lane >> 4) * 8 + (lane & 7);
    const int bkoff = ((lane >> 3) & 1) * 8;

    load_stage(0);
    load_stage(1);

    for (int s = 0; s < NSTAGE; s++) {
        if (s + 1 < NSTAGE)
            asm volatile("cp.async.wait_group 1;" ::: "memory");
        else
            asm volatile("cp.async.wait_group 0;" ::: "memory");
        __syncthreads();
        if (s + 2 < NSTAGE) load_stage(s + 2);

        const int buf = s % PIPE;
        const uint32_t ab = aoff0 + buf * BUFB;
        const uint32_t bb = boff0 + buf * BUFB;

#pragma unroll
        for (int ksub = 0; ksub < 4; ksub++) {
            uint32_t af[4][4], bf[2][4];
#pragma unroll
            for (int mt = 0; mt < 4; mt++)
                ldsm_x4(af[mt], ab + (uint32_t)((arow + mt * 16) * SA + ksub * 16 + akoff) * 2);
#pragma unroll
            for (int p = 0; p < 2; p++)
                ldsm_x4(bf[p], bb + (uint32_t)((brow + p * 16) * SA + ksub * 16 + bkoff) * 2);
#pragma unroll
            for (int mt = 0; mt < 4; mt++) {
#pragma unroll
                for (int nt = 0; nt < 4; nt++)
                    mma_bf16(acc[mt][nt], af[mt], &bf[nt >> 1][(nt & 1) * 2]);
            }
        }
    }

    const int grp = lane >> 2;
    const int tig = lane & 3;
#pragma unroll
    for (int mt = 0; mt < 4; mt++) {
#pragma unroll
        for (int nt = 0; nt < 4; nt++) {
            const int row = m0 + wm + mt * 16 + grp;
            const int col = n0 + wn + nt * 8 + tig * 2;
            float2 v0 = make_float2(acc[mt][nt][0], acc[mt][nt][1]);
            float2 v1 = make_float2(acc[mt][nt][2], acc[mt][nt][3]);
            *(float2*)&C[(size_t)row * Nn + col]       = v0;
            *(float2*)&C[(size_t)(row + 8) * Nn + col] = v1;
        }
    }
}

// ===========================================================================
// Conversion kernels
// ===========================================================================
__global__ __launch_bounds__(256)
void split_rows(const float* __restrict__ in, __nv_bfloat16* __restrict__ out, int M) {
    int idx = blockIdx.x * 256 + threadIdx.x;
    if (idx >= M * DD) return;
    int m = idx >> 10, k = idx & 1023;
    float x = in[idx];
    __nv_bfloat16 hi = __float2bfloat16(x);
    __nv_bfloat16 lo = __float2bfloat16(x - __bfloat162float(hi));
    __nv_bfloat16* o = out + (size_t)m * KP;
    o[k] = hi; o[DD + k] = lo; o[2 * DD + k] = hi;
}

__global__ __launch_bounds__(256)
void split_transpose(const float* __restrict__ W, __nv_bfloat16* __restrict__ out, int Nw) {
    __shared__ float t[32][33];
    int n0 = blockIdx.x * 32, k0 = blockIdx.y * 32;
    int tx = threadIdx.x, ty = threadIdx.y;
#pragma unroll
    for (int i = ty; i < 32; i += 8)
        t[i][tx] = W[(size_t)(k0 + i) * Nw + n0 + tx];
    __syncthreads();
#pragma unroll
    for (int i = ty; i < 32; i += 8) {
        int n = n0 + i, k = k0 + tx;
        float x = t[tx][i];
        __nv_bfloat16 hi = __float2bfloat16(x);
        __nv_bfloat16 lo = __float2bfloat16(x - __bfloat162float(hi));
        __nv_bfloat16* o = out + (size_t)n * KP;
        o[k] = hi; o[DD + k] = hi; o[2 * DD + k] = lo;
    }
}

// ===========================================================================
// Attention, tf32 mma — R4 inner loops; coalesced fused split epilogue.
// ===========================================================================
#define AT_I 128
#define AT_J 64
#define STRD 68
#define SMEM_ATTN ((AT_I + AT_J + AT_J) * STRD * (int)sizeof(float))

__global__ __launch_bounds__(256, 2)
void attn_tc(const float* __restrict__ qkv, __nv_bfloat16* __restrict__ Aout) {
    extern __shared__ float sm[];
    float* Ksm = sm;
    float* Qsm = sm + AT_I * STRD;
    float* Vsm = sm + (AT_I + AT_J) * STRD;

    const int it = blockIdx.x;
    const int bh = blockIdx.y;
    const int b = bh >> 4, h = bh & 15;
    const int i0 = it * AT_I;

    const int tid  = threadIdx.x;
    const int wid  = tid >> 5;
    const int lane = tid & 31;
    const int g = lane >> 2;
    const int t = lane & 3;
    const int wm = wid * 16;

    const size_t RS = 3 * DD;
    const float* Qg = qkv + h * EE;
    const float* Kg = qkv + DD + h * EE;
    const float* Vg = qkv + 2 * DD + h * EE;

#pragma unroll
    for (int q = 0; q < 8; q++) {
        int idx = q * 256 + tid;
        int r = idx >> 4, ec = (idx & 15) << 2;
        float4 v = *(const float4*)(Kg + (size_t)(b * NN + i0 + r) * RS + ec);
        float* d = Ksm + r * STRD + ec;
        d[0] = tf32r(v.x); d[1] = tf32r(v.y); d[2] = tf32r(v.z); d[3] = tf32r(v.w);
    }

    float m0 = -1e30f, m1 = -1e30f, l0 = 0.0f, l1 = 0.0f;
    float O[8][4];
#pragma unroll
    for (int nt = 0; nt < 8; nt++)
#pragma unroll
        for (int k = 0; k < 4; k++) O[nt][k] = 0.0f;

    const int r0g = i0 + wm + g;
    const int r1g = r0g + 8;

    const int jt0 = it * 2;
    const int nJT = NN / AT_J;

    for (int jt = jt0; jt < nJT; jt++) {
        const int j0 = jt * AT_J;
        __syncthreads();

#pragma unroll
        for (int q = 0; q < 4; q++) {
            int idx = q * 256 + tid;
            int r = idx >> 4, ec = (idx & 15) << 2;
            float4 v = *(const float4*)(Qg + (size_t)(b * NN + j0 + r) * RS + ec);
            float* d = Qsm + r * STRD + ec;
            d[0] = tf32r(v.x); d[1] = tf32r(v.y); d[2] = tf32r(v.z); d[3] = tf32r(v.w);
        }
#pragma unroll
        for (int q = 0; q < 4; q++) {
            int ec = (wid * 2 + (q >> 1)) << 2;
            int j  = ((q & 1) << 5) + lane;
            float4 v = *(const float4*)(Vg + (size_t)(b * NN + j0 + j) * RS + ec);
            Vsm[(ec + 0) * STRD + j] = tf32r(v.x);
            Vsm[(ec + 1) * STRD + j] = tf32r(v.y);
            Vsm[(ec + 2) * STRD + j] = tf32r(v.z);
            Vsm[(ec + 3) * STRD + j] = tf32r(v.w);
        }
        __syncthreads();

        float C[8][4];
#pragma unroll
        for (int nt = 0; nt < 8; nt++)
#pragma unroll
            for (int k = 0; k < 4; k++) C[nt][k] = 0.0f;

#pragma unroll
        for (int kt = 0; kt < 8; kt++) {
            float a[4];
            a[0] = Ksm[(wm + g)     * STRD + kt * 8 + t];
            a[1] = Ksm[(wm + g + 8) * STRD + kt * 8 + t];
            a[2] = Ksm[(wm + g)     * STRD + kt * 8 + t + 4];
            a[3] = Ksm[(wm + g + 8) * STRD + kt * 8 + t + 4];
#pragma unroll
            for (int nt = 0; nt < 8; nt++) {
                float b0 = Qsm[(nt * 8 + g) * STRD + kt * 8 + t];
                float b1 = Qsm[(nt * 8 + g) * STRD + kt * 8 + t + 4];
                mma_tf32(C[nt], a, b0, b1);
            }
        }

        const bool needmask = (j0 < i0 + AT_I);
        float rmax0 = -1e30f, rmax1 = -1e30f;
#pragma unroll
        for (int nt = 0; nt < 8; nt++) {
            C[nt][0] *= 0.125f; C[nt][1] *= 0.125f;
            C[nt][2] *= 0.125f; C[nt][3] *= 0.125f;
            if (needmask) {
                int c0 = j0 + nt * 8 + 2 * t;
                int c1 = c0 + 1;
                if (c0 < r0g) C[nt][0] = -1e30f;
                if (c1 < r0g) C[nt][1] = -1e30f;
                if (c0 < r1g) C[nt][2] = -1e30f;
                if (c1 < r1g) C[nt][3] = -1e30f;
            }
            rmax0 = fmaxf(rmax0, fmaxf(C[nt][0], C[nt][1]));
            rmax1 = fmaxf(rmax1, fmaxf(C[nt][2], C[nt][3]));
        }
        rmax0 = fmaxf(rmax0, __shfl_xor_sync(0xffffffffu, rmax0, 1));
        rmax0 = fmaxf(rmax0, __shfl_xor_sync(0xffffffffu, rmax0, 2));
        rmax1 = fmaxf(rmax1, __shfl_xor_sync(0xffffffffu, rmax1, 1));
        rmax1 = fmaxf(rmax1, __shfl_xor_sync(0xffffffffu, rmax1, 2));

        float mn0 = fmaxf(m0, rmax0), mn1 = fmaxf(m1, rmax1);
        float sc0 = __expf(m0 - mn0), sc1 = __expf(m1 - mn1);
        m0 = mn0; m1 = mn1;

        float rs0 = 0.0f, rs1 = 0.0f;
#pragma unroll
        for (int nt = 0; nt < 8; nt++) {
            C[nt][0] = __expf(C[nt][0] - mn0);
            C[nt][1] = __expf(C[nt][1] - mn0);
            C[nt][2] = __expf(C[nt][2] - mn1);
            C[nt][3] = __expf(C[nt][3] - mn1);
            rs0 += C[nt][0] + C[nt][1];
            rs1 += C[nt][2] + C[nt][3];
        }
        rs0 += __shfl_xor_sync(0xffffffffu, rs0, 1);
        rs0 += __shfl_xor_sync(0xffffffffu, rs0, 2);
        rs1 += __shfl_xor_sync(0xffffffffu, rs1, 1);
        rs1 += __shfl_xor_sync(0xffffffffu, rs1, 2);
        l0 = l0 * sc0 + rs0;
        l1 = l1 * sc1 + rs1;
#pragma unroll
        for (int nt = 0; nt < 8; nt++) {
            O[nt][0] *= sc0; O[nt][1] *= sc0;
            O[nt][2] *= sc1; O[nt][3] *= sc1;
        }

        const uint32_t srcA = (lane & 28) | (t >> 1);
        const uint32_t srcB = srcA + 2;
#pragma unroll
        for (int kt = 0; kt < 8; kt++) {
            float p0a = __shfl_sync(0xffffffffu, C[kt][0], srcA);
            float p1a = __shfl_sync(0xffffffffu, C[kt][1], srcA);
            float p2a = __shfl_sync(0xffffffffu, C[kt][2], srcA);
            float p3a = __shfl_sync(0xffffffffu, C[kt][3], srcA);
            float p0b = __shfl_sync(0xffffffffu, C[kt][0], srcB);
            float p1b = __shfl_sync(0xffffffffu, C[kt][1], srcB);
            float p2b = __shfl_sync(0xffffffffu, C[kt][2], srcB);
            float p3b = __shfl_sync(0xffffffffu, C[kt][3], srcB);
            float a[4];
            a[0] = tf32r((t & 1) ? p1a : p0a);
            a[1] = tf32r((t & 1) ? p3a : p2a);
            a[2] = tf32r((t & 1) ? p1b : p0b);
            a[3] = tf32r((t & 1) ? p3b : p2b);
#pragma unroll
            for (int nt = 0; nt < 8; nt++) {
                float b0 = Vsm[(nt * 8 + g) * STRD + kt * 8 + t];
                float b1 = Vsm[(nt * 8 + g) * STRD + kt * 8 + t + 4];
                mma_tf32(O[nt], a, b0, b1);
            }
        }
    }

    // ---- coalesced fused epilogue: stage O in Ksm, then uint4 bf16 stores ----
    __syncthreads();   // all warps done reading Ksm
    {
        float inv0 = 1.0f / l0, inv1 = 1.0f / l1;
#pragma unroll
        for (int nt = 0; nt < 8; nt++) {
            int col = nt * 8 + 2 * t;
            Ksm[(wm + g)     * STRD + col]     = O[nt][0] * inv0;
            Ksm[(wm + g)     * STRD + col + 1] = O[nt][1] * inv0;
            Ksm[(wm + g + 8) * STRD + col]     = O[nt][2] * inv1;
            Ksm[(wm + g + 8) * STRD + col + 1] = O[nt][3] * inv1;
        }
    }
    __syncthreads();

#pragma unroll
    for (int itr = 0; itr < 4; itr++) {
        int idx = itr * 256 + tid;         // 1024 items: 128 rows x 8 chunks
        int r  = idx >> 3;
        int c8 = (idx & 7) << 3;
        const float* s = Ksm + r * STRD + c8;
        uint32_t hw[4], lw[4];
#pragma unroll
        for (int j = 0; j < 4; j++) {
            float x0 = s[2 * j], x1 = s[2 * j + 1];
            __nv_bfloat16 h0 = __float2bfloat16(x0);
            __nv_bfloat16 h1 = __float2bfloat16(x1);
            __nv_bfloat16 e0 = __float2bfloat16(x0 - __bfloat162float(h0));
            __nv_bfloat16 e1 = __float2bfloat16(x1 - __bfloat162float(h1));
            hw[j] = pack_bf16(h0, h1);
            lw[j] = pack_bf16(e0, e1);
        }
        __nv_bfloat16* dst = Aout + (size_t)(b * NN + i0 + r) * KP + h * EE + c8;
        *(uint4*)(dst)          = *(uint4*)hw;
        *(uint4*)(dst + DD)     = *(uint4*)lw;
        *(uint4*)(dst + 2 * DD) = *(uint4*)hw;
    }
}

// ===========================================================================
extern "C" void kernel_launch(void* const* d_in, const int* in_sizes, int n_in,
                              void* d_out, int out_size) {
    const float* x    = (const float*)d_in[0];
    const float* Wqkv = (const float*)d_in[1];
    const float* Wo   = (const float*)d_in[2];
    float* out = (float*)d_out;

    float* qkv = nullptr;
    __nv_bfloat16* Abuf = nullptr;  __nv_bfloat16* Bbuf = nullptr;
    cudaGetSymbolAddress((void**)&qkv,  g_qkv);
    cudaGetSymbolAddress((void**)&Abuf, g_A);
    cudaGetSymbolAddress((void**)&Bbuf, g_B);

    cudaFuncSetAttribute(gemm_hmma, cudaFuncAttributeMaxDynamicSharedMemorySize, SMEM_GEMM);
    cudaFuncSetAttribute(attn_tc, cudaFuncAttributeMaxDynamicSharedMemorySize, SMEM_ATTN);

    // 1) x -> A' split
    split_rows<<<(MTOT * DD + 255) / 256, 256>>>(x, Abuf, MTOT);
    // 2) W_qkv -> B' split-transpose
    split_transpose<<<dim3(3 * DD / 32, DD / 32), dim3(32, 8)>>>(Wqkv, Bbuf, 3 * DD);
    // 3) QKV GEMM
    gemm_hmma<<<dim3(3 * DD / 128, MTOT / 128), 256, SMEM_GEMM>>>(Abuf, Bbuf, qkv, MTOT, 3 * DD);
    // 4) attention -> writes A' split directly (coalesced)
    attn_tc<<<dim3(NN / AT_I, BB * HH), 256, SMEM_ATTN>>>(qkv, Abuf);
    // 5) W_o -> B'
    split_transpose<<<dim3(DD / 32, DD / 32), dim3(32, 8)>>>(Wo, Bbuf, DD);
    // 6) O-proj GEMM
    gemm_hmma<<<dim3(DD / 128, MTOT / 128), 256, SMEM_GEMM>>>(Abuf, Bbuf, out, MTOT, DD);
}

// round 10
// speedup vs baseline: 1.0767x; 1.0767x over previous
#include <cuda_runtime.h>
#include <cuda_bf16.h>
#include <cstdint>
#include <math.h>

// ---------------------------------------------------------------------------
// Problem: x[4,2048,1024] f32; W_qkv[1024,3072]; W_o[1024,1024]; out[4,2048,1024]
//   1) split x -> A' bf16 [8192, 3072]  (hi | lo | hi along K)
//   2) split/transpose W_qkv -> B' bf16 [3072, 3072] (hi ; hi ; lo)
//   3) HMMA bf16 GEMM (R4 config: BK=32, PIPE=3, 256thr) -> g_qkv
//   4) tf32 mma attention -> coalesced fused split epilogue writes A'
//   5) split/transpose W_o -> B'
//   6) HMMA bf16 GEMM -> out
// ---------------------------------------------------------------------------
#define BB 4
#define NN 2048
#define DD 1024
#define HH 16
#define EE 64
#define MTOT (BB * NN)   // 8192
#define KP   3072
#define SA   40          // gemm smem row stride in bf16 (32 data + 8 pad)
#define NSTAGE 96        // KP / 32
#define PIPE 3

__device__ float         g_qkv[MTOT * 3 * DD];
__device__ __nv_bfloat16 g_A[MTOT * KP];
__device__ __nv_bfloat16 g_B[3 * DD * KP];

// ===========================================================================
__device__ __forceinline__ uint32_t smem_u32(const void* p) {
    uint32_t a;
    asm("{ .reg .u64 t; cvta.to.shared.u64 t, %1; cvt.u32.u64 %0, t; }"
        : "=r"(a) : "l"(p));
    return a;
}
__device__ __forceinline__ void cp_async16(uint32_t dst, const void* src) {
    asm volatile("cp.async.cg.shared.global [%0], [%1], 16;"
                 :: "r"(dst), "l"(src) : "memory");
}
__device__ __forceinline__ void ldsm_x4(uint32_t* r, uint32_t addr) {
    asm volatile("ldmatrix.sync.aligned.m8n8.x4.shared.b16 {%0,%1,%2,%3}, [%4];"
                 : "=r"(r[0]), "=r"(r[1]), "=r"(r[2]), "=r"(r[3]) : "r"(addr));
}
__device__ __forceinline__ void mma_bf16(float* d, const uint32_t* a, const uint32_t* b) {
    asm volatile(
        "mma.sync.aligned.m16n8k16.row.col.f32.bf16.bf16.f32 "
        "{%0,%1,%2,%3}, {%4,%5,%6,%7}, {%8,%9}, {%0,%1,%2,%3};"
        : "+f"(d[0]), "+f"(d[1]), "+f"(d[2]), "+f"(d[3])
        : "r"(a[0]), "r"(a[1]), "r"(a[2]), "r"(a[3]), "r"(b[0]), "r"(b[1]));
}
__device__ __forceinline__ float tf32r(float x) {
    asm("cvt.rna.tf32.f32 %0, %0;" : "+f"(x));
    return x;
}
__device__ __forceinline__ void mma_tf32(float* d, const float* a, float b0f, float b1f) {
    uint32_t a0 = __float_as_uint(a[0]), a1 = __float_as_uint(a[1]);
    uint32_t a2 = __float_as_uint(a[2]), a3 = __float_as_uint(a[3]);
    uint32_t b0 = __float_as_uint(b0f), b1 = __float_as_uint(b1f);
    asm volatile(
        "mma.sync.aligned.m16n8k8.row.col.f32.tf32.tf32.f32 "
        "{%0,%1,%2,%3}, {%4,%5,%6,%7}, {%8,%9}, {%0,%1,%2,%3};"
        : "+f"(d[0]), "+f"(d[1]), "+f"(d[2]), "+f"(d[3])
        : "r"(a0), "r"(a1), "r"(a2), "r"(a3), "r"(b0), "r"(b1));
}
__device__ __forceinline__ uint32_t pack_bf16(__nv_bfloat16 a, __nv_bfloat16 b) {
    __nv_bfloat162 p; p.x = a; p.y = b;
    return *reinterpret_cast<uint32_t*>(&p);
}

// ===========================================================================
// HMMA GEMM — exact R4 configuration (measured: both GEMMs ~790us)
// CTA 128x128, 8 warps of 64x32, BK=32, 3-stage cp.async ring.
// ===========================================================================
#define BUFB (128 * SA * 2)
#define SMEM_GEMM (PIPE * 2 * BUFB)

__global__ __launch_bounds__(256, 2)
void gemm_hmma(const __nv_bfloat16* __restrict__ A,
               const __nv_bfloat16* __restrict__ B,
               float* __restrict__ C, int M, int Nn) {
    extern __shared__ __nv_bfloat16 smbf[];
    const int tid  = threadIdx.x;
    const int wid  = tid >> 5;
    const int lane = tid & 31;
    const int m0 = blockIdx.y * 128;
    const int n0 = blockIdx.x * 128;
    const int wm = (wid >> 2) * 64;
    const int wn = (wid & 3) * 32;

    const uint32_t sbase = smem_u32(smbf);
    const uint32_t aoff0 = sbase;
    const uint32_t boff0 = sbase + PIPE * BUFB;

    const __nv_bfloat16* Ag = A + (size_t)m0 * KP;
    const __nv_bfloat16* Bg = B + (size_t)n0 * KP;

    const int lr  = tid >> 1;
    const int lkc = (tid & 1) * 2;

    auto load_stage = [&](int s) {
        const int buf = s % PIPE;
        const uint32_t ab = aoff0 + buf * BUFB;
        const uint32_t bb = boff0 + buf * BUFB;
        const int k0 = s * 32;
#pragma unroll
        for (int j = 0; j < 2; j++) {
            const int kc = lkc + j;
            const uint32_t doff = (uint32_t)(lr * SA + kc * 8) * 2;
            cp_async16(ab + doff, Ag + (size_t)lr * KP + k0 + kc * 8);
            cp_async16(bb + doff, Bg + (size_t)lr * KP + k0 + kc * 8);
        }
        asm volatile("cp.async.commit_group;" ::: "memory");
    };

    float acc[4][4][4];
#pragma unroll
    for (int i = 0; i < 4; i++)
#pragma unroll
        for (int j = 0; j < 4; j++)
#pragma unroll
            for (int k = 0; k < 4; k++) acc[i][j][k] = 0.0f;

    const int arow  = wm + (lane & 15);
    const int akoff = (lane >> 4) * 8;
    const int brow  = wn + (lane >> 4) * 8 + (lane & 7);
    const int bkoff = ((lane >> 3) & 1) * 8;

    load_stage(0);
    load_stage(1);

    for (int s = 0; s < NSTAGE; s++) {
        if (s + 1 < NSTAGE)
            asm volatile("cp.async.wait_group 1;" ::: "memory");
        else
            asm volatile("cp.async.wait_group 0;" ::: "memory");
        __syncthreads();
        if (s + 2 < NSTAGE) load_stage(s + 2);

        const int buf = s % PIPE;
        const uint32_t ab = aoff0 + buf * BUFB;
        const uint32_t bb = boff0 + buf * BUFB;

#pragma unroll
        for (int ksub = 0; ksub < 2; ksub++) {
            uint32_t af[4][4], bf[2][4];
#pragma unroll
            for (int mt = 0; mt < 4; mt++)
                ldsm_x4(af[mt], ab + (uint32_t)((arow + mt * 16) * SA + ksub * 16 + akoff) * 2);
#pragma unroll
            for (int p = 0; p < 2; p++)
                ldsm_x4(bf[p], bb + (uint32_t)((brow + p * 16) * SA + ksub * 16 + bkoff) * 2);
#pragma unroll
            for (int mt = 0; mt < 4; mt++) {
#pragma unroll
                for (int nt = 0; nt < 4; nt++)
                    mma_bf16(acc[mt][nt], af[mt], &bf[nt >> 1][(nt & 1) * 2]);
            }
        }
    }

    const int grp = lane >> 2;
    const int tig = lane & 3;
#pragma unroll
    for (int mt = 0; mt < 4; mt++) {
#pragma unroll
        for (int nt = 0; nt < 4; nt++) {
            const int row = m0 + wm + mt * 16 + grp;
            const int col = n0 + wn + nt * 8 + tig * 2;
            float2 v0 = make_float2(acc[mt][nt][0], acc[mt][nt][1]);
            float2 v1 = make_float2(acc[mt][nt][2], acc[mt][nt][3]);
            *(float2*)&C[(size_t)row * Nn + col]       = v0;
            *(float2*)&C[(size_t)(row + 8) * Nn + col] = v1;
        }
    }
}

// ===========================================================================
// Conversion kernels
// ===========================================================================
__global__ __launch_bounds__(256)
void split_rows(const float* __restrict__ in, __nv_bfloat16* __restrict__ out, int M) {
    int idx = blockIdx.x * 256 + threadIdx.x;
    if (idx >= M * DD) return;
    int m = idx >> 10, k = idx & 1023;
    float x = in[idx];
    __nv_bfloat16 hi = __float2bfloat16(x);
    __nv_bfloat16 lo = __float2bfloat16(x - __bfloat162float(hi));
    __nv_bfloat16* o = out + (size_t)m * KP;
    o[k] = hi; o[DD + k] = lo; o[2 * DD + k] = hi;
}

__global__ __launch_bounds__(256)
void split_transpose(const float* __restrict__ W, __nv_bfloat16* __restrict__ out, int Nw) {
    __shared__ float t[32][33];
    int n0 = blockIdx.x * 32, k0 = blockIdx.y * 32;
    int tx = threadIdx.x, ty = threadIdx.y;
#pragma unroll
    for (int i = ty; i < 32; i += 8)
        t[i][tx] = W[(size_t)(k0 + i) * Nw + n0 + tx];
    __syncthreads();
#pragma unroll
    for (int i = ty; i < 32; i += 8) {
        int n = n0 + i, k = k0 + tx;
        float x = t[tx][i];
        __nv_bfloat16 hi = __float2bfloat16(x);
        __nv_bfloat16 lo = __float2bfloat16(x - __bfloat162float(hi));
        __nv_bfloat16* o = out + (size_t)n * KP;
        o[k] = hi; o[DD + k] = hi; o[2 * DD + k] = lo;
    }
}

// ===========================================================================
// Attention — exact R9 kernel (measured 390us incl. fused split epilogue)
// ===========================================================================
#define AT_I 128
#define AT_J 64
#define STRD 68
#define SMEM_ATTN ((AT_I + AT_J + AT_J) * STRD * (int)sizeof(float))

__global__ __launch_bounds__(256, 2)
void attn_tc(const float* __restrict__ qkv, __nv_bfloat16* __restrict__ Aout) {
    extern __shared__ float sm[];
    float* Ksm = sm;
    float* Qsm = sm + AT_I * STRD;
    float* Vsm = sm + (AT_I + AT_J) * STRD;

    const int it = blockIdx.x;
    const int bh = blockIdx.y;
    const int b = bh >> 4, h = bh & 15;
    const int i0 = it * AT_I;

    const int tid  = threadIdx.x;
    const int wid  = tid >> 5;
    const int lane = tid & 31;
    const int g = lane >> 2;
    const int t = lane & 3;
    const int wm = wid * 16;

    const size_t RS = 3 * DD;
    const float* Qg = qkv + h * EE;
    const float* Kg = qkv + DD + h * EE;
    const float* Vg = qkv + 2 * DD + h * EE;

#pragma unroll
    for (int q = 0; q < 8; q++) {
        int idx = q * 256 + tid;
        int r = idx >> 4, ec = (idx & 15) << 2;
        float4 v = *(const float4*)(Kg + (size_t)(b * NN + i0 + r) * RS + ec);
        float* d = Ksm + r * STRD + ec;
        d[0] = tf32r(v.x); d[1] = tf32r(v.y); d[2] = tf32r(v.z); d[3] = tf32r(v.w);
    }

    float m0 = -1e30f, m1 = -1e30f, l0 = 0.0f, l1 = 0.0f;
    float O[8][4];
#pragma unroll
    for (int nt = 0; nt < 8; nt++)
#pragma unroll
        for (int k = 0; k < 4; k++) O[nt][k] = 0.0f;

    const int r0g = i0 + wm + g;
    const int r1g = r0g + 8;

    const int jt0 = it * 2;
    const int nJT = NN / AT_J;

    for (int jt = jt0; jt < nJT; jt++) {
        const int j0 = jt * AT_J;
        __syncthreads();

#pragma unroll
        for (int q = 0; q < 4; q++) {
            int idx = q * 256 + tid;
            int r = idx >> 4, ec = (idx & 15) << 2;
            float4 v = *(const float4*)(Qg + (size_t)(b * NN + j0 + r) * RS + ec);
            float* d = Qsm + r * STRD + ec;
            d[0] = tf32r(v.x); d[1] = tf32r(v.y); d[2] = tf32r(v.z); d[3] = tf32r(v.w);
        }
#pragma unroll
        for (int q = 0; q < 4; q++) {
            int ec = (wid * 2 + (q >> 1)) << 2;
            int j  = ((q & 1) << 5) + lane;
            float4 v = *(const float4*)(Vg + (size_t)(b * NN + j0 + j) * RS + ec);
            Vsm[(ec + 0) * STRD + j] = tf32r(v.x);
            Vsm[(ec + 1) * STRD + j] = tf32r(v.y);
            Vsm[(ec + 2) * STRD + j] = tf32r(v.z);
            Vsm[(ec + 3) * STRD + j] = tf32r(v.w);
        }
        __syncthreads();

        float C[8][4];
#pragma unroll
        for (int nt = 0; nt < 8; nt++)
#pragma unroll
            for (int k = 0; k < 4; k++) C[nt][k] = 0.0f;

#pragma unroll
        for (int kt = 0; kt < 8; kt++) {
            float a[4];
            a[0] = Ksm[(wm + g)     * STRD + kt * 8 + t];
            a[1] = Ksm[(wm + g + 8) * STRD + kt * 8 + t];
            a[2] = Ksm[(wm + g)     * STRD + kt * 8 + t + 4];
            a[3] = Ksm[(wm + g + 8) * STRD + kt * 8 + t + 4];
#pragma unroll
            for (int nt = 0; nt < 8; nt++) {
                float b0 = Qsm[(nt * 8 + g) * STRD + kt * 8 + t];
                float b1 = Qsm[(nt * 8 + g) * STRD + kt * 8 + t + 4];
                mma_tf32(C[nt], a, b0, b1);
            }
        }

        const bool needmask = (j0 < i0 + AT_I);
        float rmax0 = -1e30f, rmax1 = -1e30f;
#pragma unroll
        for (int nt = 0; nt < 8; nt++) {
            C[nt][0] *= 0.125f; C[nt][1] *= 0.125f;
            C[nt][2] *= 0.125f; C[nt][3] *= 0.125f;
            if (needmask) {
                int c0 = j0 + nt * 8 + 2 * t;
                int c1 = c0 + 1;
                if (c0 < r0g) C[nt][0] = -1e30f;
                if (c1 < r0g) C[nt][1] = -1e30f;
                if (c0 < r1g) C[nt][2] = -1e30f;
                if (c1 < r1g) C[nt][3] = -1e30f;
            }
            rmax0 = fmaxf(rmax0, fmaxf(C[nt][0], C[nt][1]));
            rmax1 = fmaxf(rmax1, fmaxf(C[nt][2], C[nt][3]));
        }
        rmax0 = fmaxf(rmax0, __shfl_xor_sync(0xffffffffu, rmax0, 1));
        rmax0 = fmaxf(rmax0, __shfl_xor_sync(0xffffffffu, rmax0, 2));
        rmax1 = fmaxf(rmax1, __shfl_xor_sync(0xffffffffu, rmax1, 1));
        rmax1 = fmaxf(rmax1, __shfl_xor_sync(0xffffffffu, rmax1, 2));

        float mn0 = fmaxf(m0, rmax0), mn1 = fmaxf(m1, rmax1);
        float sc0 = __expf(m0 - mn0), sc1 = __expf(m1 - mn1);
        m0 = mn0; m1 = mn1;

        float rs0 = 0.0f, rs1 = 0.0f;
#pragma unroll
        for (int nt = 0; nt < 8; nt++) {
            C[nt][0] = __expf(C[nt][0] - mn0);
            C[nt][1] = __expf(C[nt][1] - mn0);
            C[nt][2] = __expf(C[nt][2] - mn1);
            C[nt][3] = __expf(C[nt][3] - mn1);
            rs0 += C[nt][0] + C[nt][1];
            rs1 += C[nt][2] + C[nt][3];
        }
        rs0 += __shfl_xor_sync(0xffffffffu, rs0, 1);
        rs0 += __shfl_xor_sync(0xffffffffu, rs0, 2);
        rs1 += __shfl_xor_sync(0xffffffffu, rs1, 1);
        rs1 += __shfl_xor_sync(0xffffffffu, rs1, 2);
        l0 = l0 * sc0 + rs0;
        l1 = l1 * sc1 + rs1;
#pragma unroll
        for (int nt = 0; nt < 8; nt++) {
            O[nt][0] *= sc0; O[nt][1] *= sc0;
            O[nt][2] *= sc1; O[nt][3] *= sc1;
        }

        const uint32_t srcA = (lane & 28) | (t >> 1);
        const uint32_t srcB = srcA + 2;
#pragma unroll
        for (int kt = 0; kt < 8; kt++) {
            float p0a = __shfl_sync(0xffffffffu, C[kt][0], srcA);
            float p1a = __shfl_sync(0xffffffffu, C[kt][1], srcA);
            float p2a = __shfl_sync(0xffffffffu, C[kt][2], srcA);
            float p3a = __shfl_sync(0xffffffffu, C[kt][3], srcA);
            float p0b = __shfl_sync(0xffffffffu, C[kt][0], srcB);
            float p1b = __shfl_sync(0xffffffffu, C[kt][1], srcB);
            float p2b = __shfl_sync(0xffffffffu, C[kt][2], srcB);
            float p3b = __shfl_sync(0xffffffffu, C[kt][3], srcB);
            float a[4];
            a[0] = tf32r((t & 1) ? p1a : p0a);
            a[1] = tf32r((t & 1) ? p3a : p2a);
            a[2] = tf32r((t & 1) ? p1b : p0b);
            a[3] = tf32r((t & 1) ? p3b : p2b);
#pragma unroll
            for (int nt = 0; nt < 8; nt++) {
                float b0 = Vsm[(nt * 8 + g) * STRD + kt * 8 + t];
                float b1 = Vsm[(nt * 8 + g) * STRD + kt * 8 + t + 4];
                mma_tf32(O[nt], a, b0, b1);
            }
        }
    }

    // ---- coalesced fused epilogue: stage O in Ksm, then uint4 bf16 stores ----
    __syncthreads();
    {
        float inv0 = 1.0f / l0, inv1 = 1.0f / l1;
#pragma unroll
        for (int nt = 0; nt < 8; nt++) {
            int col = nt * 8 + 2 * t;
            Ksm[(wm + g)     * STRD + col]     = O[nt][0] * inv0;
            Ksm[(wm + g)     * STRD + col + 1] = O[nt][1] * inv0;
            Ksm[(wm + g + 8) * STRD + col]     = O[nt][2] * inv1;
            Ksm[(wm + g + 8) * STRD + col + 1] = O[nt][3] * inv1;
        }
    }
    __syncthreads();

#pragma unroll
    for (int itr = 0; itr < 4; itr++) {
        int idx = itr * 256 + tid;
        int r  = idx >> 3;
        int c8 = (idx & 7) << 3;
        const float* s = Ksm + r * STRD + c8;
        uint32_t hw[4], lw[4];
#pragma unroll
        for (int j = 0; j < 4; j++) {
            float x0 = s[2 * j], x1 = s[2 * j + 1];
            __nv_bfloat16 h0 = __float2bfloat16(x0);
            __nv_bfloat16 h1 = __float2bfloat16(x1);
            __nv_bfloat16 e0 = __float2bfloat16(x0 - __bfloat162float(h0));
            __nv_bfloat16 e1 = __float2bfloat16(x1 - __bfloat162float(h1));
            hw[j] = pack_bf16(h0, h1);
            lw[j] = pack_bf16(e0, e1);
        }
        __nv_bfloat16* dst = Aout + (size_t)(b * NN + i0 + r) * KP + h * EE + c8;
        *(uint4*)(dst)          = *(uint4*)hw;
        *(uint4*)(dst + DD)     = *(uint4*)lw;
        *(uint4*)(dst + 2 * DD) = *(uint4*)hw;
    }
}

// ===========================================================================
extern "C" void kernel_launch(void* const* d_in, const int* in_sizes, int n_in,
                              void* d_out, int out_size) {
    const float* x    = (const float*)d_in[0];
    const float* Wqkv = (const float*)d_in[1];
    const float* Wo   = (const float*)d_in[2];
    float* out = (float*)d_out;

    float* qkv = nullptr;
    __nv_bfloat16* Abuf = nullptr;  __nv_bfloat16* Bbuf = nullptr;
    cudaGetSymbolAddress((void**)&qkv,  g_qkv);
    cudaGetSymbolAddress((void**)&Abuf, g_A);
    cudaGetSymbolAddress((void**)&Bbuf, g_B);

    cudaFuncSetAttribute(gemm_hmma, cudaFuncAttributeMaxDynamicSharedMemorySize, SMEM_GEMM);
    cudaFuncSetAttribute(attn_tc, cudaFuncAttributeMaxDynamicSharedMemorySize, SMEM_ATTN);

    // 1) x -> A' split
    split_rows<<<(MTOT * DD + 255) / 256, 256>>>(x, Abuf, MTOT);
    // 2) W_qkv -> B' split-transpose
    split_transpose<<<dim3(3 * DD / 32, DD / 32), dim3(32, 8)>>>(Wqkv, Bbuf, 3 * DD);
    // 3) QKV GEMM
    gemm_hmma<<<dim3(3 * DD / 128, MTOT / 128), 256, SMEM_GEMM>>>(Abuf, Bbuf, qkv, MTOT, 3 * DD);
    // 4) attention -> writes A' split directly (coalesced)
    attn_tc<<<dim3(NN / AT_I, BB * HH), 256, SMEM_ATTN>>>(qkv, Abuf);
    // 5) W_o -> B'
    split_transpose<<<dim3(DD / 32, DD / 32), dim3(32, 8)>>>(Wo, Bbuf, DD);
    // 6) O-proj GEMM
    gemm_hmma<<<dim3(DD / 128, MTOT / 128), 256, SMEM_GEMM>>>(Abuf, Bbuf, out, MTOT, DD);
}

// round 11
// speedup vs baseline: 1.1500x; 1.0680x over previous
#include <cuda_runtime.h>
#include <cuda_bf16.h>
#include <cstdint>
#include <math.h>

// ---------------------------------------------------------------------------
// Problem: x[4,2048,1024] f32; W_qkv[1024,3072]; W_o[1024,1024]; out[4,2048,1024]
//   1) split x -> A' bf16 [8192, 3072]  (hi | lo | hi along K)
//   2) split/transpose W_qkv -> B' bf16 [3072, 3072] (hi ; hi ; lo)
//   3) HMMA bf16 GEMM (R4 config) -> g_qkv
//   4) tf32 mma attention, cp.async double-buffered Q/V -> fused split to A'
//   5) split/transpose W_o -> B'
//   6) HMMA bf16 GEMM -> out
// ---------------------------------------------------------------------------
#define BB 4
#define NN 2048
#define DD 1024
#define HH 16
#define EE 64
#define MTOT (BB * NN)   // 8192
#define KP   3072
#define SA   40          // gemm smem row stride in bf16 (32 data + 8 pad)
#define NSTAGE 96        // KP / 32
#define PIPE 3

__device__ float         g_qkv[MTOT * 3 * DD];
__device__ __nv_bfloat16 g_A[MTOT * KP];
__device__ __nv_bfloat16 g_B[3 * DD * KP];

// ===========================================================================
__device__ __forceinline__ uint32_t smem_u32(const void* p) {
    uint32_t a;
    asm("{ .reg .u64 t; cvta.to.shared.u64 t, %1; cvt.u32.u64 %0, t; }"
        : "=r"(a) : "l"(p));
    return a;
}
__device__ __forceinline__ void cp_async16(uint32_t dst, const void* src) {
    asm volatile("cp.async.cg.shared.global [%0], [%1], 16;"
                 :: "r"(dst), "l"(src) : "memory");
}
__device__ __forceinline__ void ldsm_x4(uint32_t* r, uint32_t addr) {
    asm volatile("ldmatrix.sync.aligned.m8n8.x4.shared.b16 {%0,%1,%2,%3}, [%4];"
                 : "=r"(r[0]), "=r"(r[1]), "=r"(r[2]), "=r"(r[3]) : "r"(addr));
}
__device__ __forceinline__ void mma_bf16(float* d, const uint32_t* a, const uint32_t* b) {
    asm volatile(
        "mma.sync.aligned.m16n8k16.row.col.f32.bf16.bf16.f32 "
        "{%0,%1,%2,%3}, {%4,%5,%6,%7}, {%8,%9}, {%0,%1,%2,%3};"
        : "+f"(d[0]), "+f"(d[1]), "+f"(d[2]), "+f"(d[3])
        : "r"(a[0]), "r"(a[1]), "r"(a[2]), "r"(a[3]), "r"(b[0]), "r"(b[1]));
}
__device__ __forceinline__ float tf32r(float x) {
    asm("cvt.rna.tf32.f32 %0, %0;" : "+f"(x));
    return x;
}
__device__ __forceinline__ void mma_tf32(float* d, const float* a, float b0f, float b1f) {
    uint32_t a0 = __float_as_uint(a[0]), a1 = __float_as_uint(a[1]);
    uint32_t a2 = __float_as_uint(a[2]), a3 = __float_as_uint(a[3]);
    uint32_t b0 = __float_as_uint(b0f), b1 = __float_as_uint(b1f);
    asm volatile(
        "mma.sync.aligned.m16n8k8.row.col.f32.tf32.tf32.f32 "
        "{%0,%1,%2,%3}, {%4,%5,%6,%7}, {%8,%9}, {%0,%1,%2,%3};"
        : "+f"(d[0]), "+f"(d[1]), "+f"(d[2]), "+f"(d[3])
        : "r"(a0), "r"(a1), "r"(a2), "r"(a3), "r"(b0), "r"(b1));
}
__device__ __forceinline__ uint32_t pack_bf16(__nv_bfloat16 a, __nv_bfloat16 b) {
    __nv_bfloat162 p; p.x = a; p.y = b;
    return *reinterpret_cast<uint32_t*>(&p);
}

// ===========================================================================
// HMMA GEMM — exact R4 configuration (measured ~790us for both GEMMs)
// ===========================================================================
#define BUFB (128 * SA * 2)
#define SMEM_GEMM (PIPE * 2 * BUFB)

__global__ __launch_bounds__(256, 2)
void gemm_hmma(const __nv_bfloat16* __restrict__ A,
               const __nv_bfloat16* __restrict__ B,
               float* __restrict__ C, int M, int Nn) {
    extern __shared__ __nv_bfloat16 smbf[];
    const int tid  = threadIdx.x;
    const int wid  = tid >> 5;
    const int lane = tid & 31;
    const int m0 = blockIdx.y * 128;
    const int n0 = blockIdx.x * 128;
    const int wm = (wid >> 2) * 64;
    const int wn = (wid & 3) * 32;

    const uint32_t sbase = smem_u32(smbf);
    const uint32_t aoff0 = sbase;
    const uint32_t boff0 = sbase + PIPE * BUFB;

    const __nv_bfloat16* Ag = A + (size_t)m0 * KP;
    const __nv_bfloat16* Bg = B + (size_t)n0 * KP;

    const int lr  = tid >> 1;
    const int lkc = (tid & 1) * 2;

    auto load_stage = [&](int s) {
        const int buf = s % PIPE;
        const uint32_t ab = aoff0 + buf * BUFB;
        const uint32_t bb = boff0 + buf * BUFB;
        const int k0 = s * 32;
#pragma unroll
        for (int j = 0; j < 2; j++) {
            const int kc = lkc + j;
            const uint32_t doff = (uint32_t)(lr * SA + kc * 8) * 2;
            cp_async16(ab + doff, Ag + (size_t)lr * KP + k0 + kc * 8);
            cp_async16(bb + doff, Bg + (size_t)lr * KP + k0 + kc * 8);
        }
        asm volatile("cp.async.commit_group;" ::: "memory");
    };

    float acc[4][4][4];
#pragma unroll
    for (int i = 0; i < 4; i++)
#pragma unroll
        for (int j = 0; j < 4; j++)
#pragma unroll
            for (int k = 0; k < 4; k++) acc[i][j][k] = 0.0f;

    const int arow  = wm + (lane & 15);
    const int akoff = (lane >> 4) * 8;
    const int brow  = wn + (lane >> 4) * 8 + (lane & 7);
    const int bkoff = ((lane >> 3) & 1) * 8;

    load_stage(0);
    load_stage(1);

    for (int s = 0; s < NSTAGE; s++) {
        if (s + 1 < NSTAGE)
            asm volatile("cp.async.wait_group 1;" ::: "memory");
        else
            asm volatile("cp.async.wait_group 0;" ::: "memory");
        __syncthreads();
        if (s + 2 < NSTAGE) load_stage(s + 2);

        const int buf = s % PIPE;
        const uint32_t ab = aoff0 + buf * BUFB;
        const uint32_t bb = boff0 + buf * BUFB;

#pragma unroll
        for (int ksub = 0; ksub < 2; ksub++) {
            uint32_t af[4][4], bf[2][4];
#pragma unroll
            for (int mt = 0; mt < 4; mt++)
                ldsm_x4(af[mt], ab + (uint32_t)((arow + mt * 16) * SA + ksub * 16 + akoff) * 2);
#pragma unroll
            for (int p = 0; p < 2; p++)
                ldsm_x4(bf[p], bb + (uint32_t)((brow + p * 16) * SA + ksub * 16 + bkoff) * 2);
#pragma unroll
            for (int mt = 0; mt < 4; mt++) {
#pragma unroll
                for (int nt = 0; nt < 4; nt++)
                    mma_bf16(acc[mt][nt], af[mt], &bf[nt >> 1][(nt & 1) * 2]);
            }
        }
    }

    const int grp = lane >> 2;
    const int tig = lane & 3;
#pragma unroll
    for (int mt = 0; mt < 4; mt++) {
#pragma unroll
        for (int nt = 0; nt < 4; nt++) {
            const int row = m0 + wm + mt * 16 + grp;
            const int col = n0 + wn + nt * 8 + tig * 2;
            float2 v0 = make_float2(acc[mt][nt][0], acc[mt][nt][1]);
            float2 v1 = make_float2(acc[mt][nt][2], acc[mt][nt][3]);
            *(float2*)&C[(size_t)row * Nn + col]       = v0;
            *(float2*)&C[(size_t)(row + 8) * Nn + col] = v1;
        }
    }
}

// ===========================================================================
// Conversion kernels
// ===========================================================================
__global__ __launch_bounds__(256)
void split_rows(const float* __restrict__ in, __nv_bfloat16* __restrict__ out, int M) {
    int idx = blockIdx.x * 256 + threadIdx.x;
    if (idx >= M * DD) return;
    int m = idx >> 10, k = idx & 1023;
    float x = in[idx];
    __nv_bfloat16 hi = __float2bfloat16(x);
    __nv_bfloat16 lo = __float2bfloat16(x - __bfloat162float(hi));
    __nv_bfloat16* o = out + (size_t)m * KP;
    o[k] = hi; o[DD + k] = lo; o[2 * DD + k] = hi;
}

__global__ __launch_bounds__(256)
void split_transpose(const float* __restrict__ W, __nv_bfloat16* __restrict__ out, int Nw) {
    __shared__ float t[32][33];
    int n0 = blockIdx.x * 32, k0 = blockIdx.y * 32;
    int tx = threadIdx.x, ty = threadIdx.y;
#pragma unroll
    for (int i = ty; i < 32; i += 8)
        t[i][tx] = W[(size_t)(k0 + i) * Nw + n0 + tx];
    __syncthreads();
#pragma unroll
    for (int i = ty; i < 32; i += 8) {
        int n = n0 + i, k = k0 + tx;
        float x = t[tx][i];
        __nv_bfloat16 hi = __float2bfloat16(x);
        __nv_bfloat16 lo = __float2bfloat16(x - __bfloat162float(hi));
        __nv_bfloat16* o = out + (size_t)n * KP;
        o[k] = hi; o[DD + k] = hi; o[2 * DD + k] = lo;
    }
}

// ===========================================================================
// Attention, tf32 mma, cp.async double-buffered Q/V prefetch.
// K: loaded once, rna-rounded. Q/V: raw fp32 via cp.async (HW tf32 truncation).
// V stored row-major [j][e] stride 72 (conflict-free b-frag loads, no transpose).
// Fused coalesced bf16-split epilogue writes A'.
// ===========================================================================
#define AT_I 128
#define AT_J 64
#define STRD 68
#define VSTR 72
#define QBUF (AT_J * STRD)               // floats per Q buffer
#define VBUF (AT_J * VSTR)               // floats per V buffer
#define SMEM_ATTN ((AT_I * STRD + 2 * QBUF + 2 * VBUF) * (int)sizeof(float))

__global__ __launch_bounds__(256, 2)
void attn_tc(const float* __restrict__ qkv, __nv_bfloat16* __restrict__ Aout) {
    extern __shared__ float sm[];
    float* Ksm = sm;                               // [128][STRD]
    float* Q2  = sm + AT_I * STRD;                 // [2][64][STRD]
    float* V2  = Q2 + 2 * QBUF;                    // [2][64][VSTR]

    const uint32_t sbase = smem_u32(sm);
    const uint32_t q2off = sbase + (uint32_t)(AT_I * STRD) * 4;
    const uint32_t v2off = q2off + (uint32_t)(2 * QBUF) * 4;

    const int it = blockIdx.x;
    const int bh = blockIdx.y;
    const int b = bh >> 4, h = bh & 15;
    const int i0 = it * AT_I;

    const int tid  = threadIdx.x;
    const int wid  = tid >> 5;
    const int lane = tid & 31;
    const int g = lane >> 2;
    const int t = lane & 3;
    const int wm = wid * 16;

    const size_t RS = 3 * DD;
    const float* Qg = qkv + h * EE;
    const float* Kg = qkv + DD + h * EE;
    const float* Vg = qkv + 2 * DD + h * EE;

    const int jt0 = it * 2;
    const int nJT = NN / AT_J;

    // cp.async Q/V tile loader: 64 rows x 64 floats, 16B chunks.
    // Q: stride 68 floats (272B). V: stride 72 floats (288B), row-major [j][e].
    auto prefetch_qv = [&](int jt, int buf) {
        const int j0 = jt * AT_J;
#pragma unroll
        for (int i = 0; i < 4; i++) {
            int idx = i * 256 + tid;         // 1024 chunks
            int r = idx >> 4;                // row 0..63
            int c = idx & 15;                // 16B chunk 0..15
            const float* qsrc = Qg + (size_t)(b * NN + j0 + r) * RS + c * 4;
            const float* vsrc = Vg + (size_t)(b * NN + j0 + r) * RS + c * 4;
            cp_async16(q2off + (uint32_t)(buf * QBUF + r * STRD) * 4 + c * 16, qsrc);
            cp_async16(v2off + (uint32_t)(buf * VBUF + r * VSTR) * 4 + c * 16, vsrc);
        }
        asm volatile("cp.async.commit_group;" ::: "memory");
    };

    // kick off first Q/V prefetch before the K load (overlap)
    prefetch_qv(jt0, 0);

    // ---- load K tile once (rna-rounded) ----
#pragma unroll
    for (int q = 0; q < 8; q++) {
        int idx = q * 256 + tid;
        int r = idx >> 4, ec = (idx & 15) << 2;
        float4 v = *(const float4*)(Kg + (size_t)(b * NN + i0 + r) * RS + ec);
        float* d = Ksm + r * STRD + ec;
        d[0] = tf32r(v.x); d[1] = tf32r(v.y); d[2] = tf32r(v.z); d[3] = tf32r(v.w);
    }

    float m0 = -1e30f, m1 = -1e30f, l0 = 0.0f, l1 = 0.0f;
    float O[8][4];
#pragma unroll
    for (int nt = 0; nt < 8; nt++)
#pragma unroll
        for (int k = 0; k < 4; k++) O[nt][k] = 0.0f;

    const int r0g = i0 + wm + g;
    const int r1g = r0g + 8;

    for (int jt = jt0; jt < nJT; jt++) {
        const int j0 = jt * AT_J;
        const int buf = (jt - jt0) & 1;

        asm volatile("cp.async.wait_group 0;" ::: "memory");
        __syncthreads();
        if (jt + 1 < nJT) prefetch_qv(jt + 1, buf ^ 1);

        const float* Qb = Q2 + buf * QBUF;
        const float* Vb = V2 + buf * VBUF;

        // ---- S = K_i . Q_j ----
        float C[8][4];
#pragma unroll
        for (int nt = 0; nt < 8; nt++)
#pragma unroll
            for (int k = 0; k < 4; k++) C[nt][k] = 0.0f;

#pragma unroll
        for (int kt = 0; kt < 8; kt++) {
            float a[4];
            a[0] = Ksm[(wm + g)     * STRD + kt * 8 + t];
            a[1] = Ksm[(wm + g + 8) * STRD + kt * 8 + t];
            a[2] = Ksm[(wm + g)     * STRD + kt * 8 + t + 4];
            a[3] = Ksm[(wm + g + 8) * STRD + kt * 8 + t + 4];
#pragma unroll
            for (int nt = 0; nt < 8; nt++) {
                float b0 = Qb[(nt * 8 + g) * STRD + kt * 8 + t];
                float b1 = Qb[(nt * 8 + g) * STRD + kt * 8 + t + 4];
                mma_tf32(C[nt], a, b0, b1);
            }
        }

        // ---- scale + mask ----
        const bool needmask = (j0 < i0 + AT_I);
        float rmax0 = -1e30f, rmax1 = -1e30f;
#pragma unroll
        for (int nt = 0; nt < 8; nt++) {
            C[nt][0] *= 0.125f; C[nt][1] *= 0.125f;
            C[nt][2] *= 0.125f; C[nt][3] *= 0.125f;
            if (needmask) {
                int c0 = j0 + nt * 8 + 2 * t;
                int c1 = c0 + 1;
                if (c0 < r0g) C[nt][0] = -1e30f;
                if (c1 < r0g) C[nt][1] = -1e30f;
                if (c0 < r1g) C[nt][2] = -1e30f;
                if (c1 < r1g) C[nt][3] = -1e30f;
            }
            rmax0 = fmaxf(rmax0, fmaxf(C[nt][0], C[nt][1]));
            rmax1 = fmaxf(rmax1, fmaxf(C[nt][2], C[nt][3]));
        }
        rmax0 = fmaxf(rmax0, __shfl_xor_sync(0xffffffffu, rmax0, 1));
        rmax0 = fmaxf(rmax0, __shfl_xor_sync(0xffffffffu, rmax0, 2));
        rmax1 = fmaxf(rmax1, __shfl_xor_sync(0xffffffffu, rmax1, 1));
        rmax1 = fmaxf(rmax1, __shfl_xor_sync(0xffffffffu, rmax1, 2));

        float mn0 = fmaxf(m0, rmax0), mn1 = fmaxf(m1, rmax1);
        float sc0 = __expf(m0 - mn0), sc1 = __expf(m1 - mn1);
        m0 = mn0; m1 = mn1;

        float rs0 = 0.0f, rs1 = 0.0f;
#pragma unroll
        for (int nt = 0; nt < 8; nt++) {
            C[nt][0] = __expf(C[nt][0] - mn0);
            C[nt][1] = __expf(C[nt][1] - mn0);
            C[nt][2] = __expf(C[nt][2] - mn1);
            C[nt][3] = __expf(C[nt][3] - mn1);
            rs0 += C[nt][0] + C[nt][1];
            rs1 += C[nt][2] + C[nt][3];
        }
        rs0 += __shfl_xor_sync(0xffffffffu, rs0, 1);
        rs0 += __shfl_xor_sync(0xffffffffu, rs0, 2);
        rs1 += __shfl_xor_sync(0xffffffffu, rs1, 1);
        rs1 += __shfl_xor_sync(0xffffffffu, rs1, 2);
        l0 = l0 * sc0 + rs0;
        l1 = l1 * sc1 + rs1;
#pragma unroll
        for (int nt = 0; nt < 8; nt++) {
            O[nt][0] *= sc0; O[nt][1] *= sc0;
            O[nt][2] *= sc1; O[nt][3] *= sc1;
        }

        // ---- O += P @ V  (V row-major [j][e], stride 72) ----
        const uint32_t srcA = (lane & 28) | (t >> 1);
        const uint32_t srcB = srcA + 2;
#pragma unroll
        for (int kt = 0; kt < 8; kt++) {
            float p0a = __shfl_sync(0xffffffffu, C[kt][0], srcA);
            float p1a = __shfl_sync(0xffffffffu, C[kt][1], srcA);
            float p2a = __shfl_sync(0xffffffffu, C[kt][2], srcA);
            float p3a = __shfl_sync(0xffffffffu, C[kt][3], srcA);
            float p0b = __shfl_sync(0xffffffffu, C[kt][0], srcB);
            float p1b = __shfl_sync(0xffffffffu, C[kt][1], srcB);
            float p2b = __shfl_sync(0xffffffffu, C[kt][2], srcB);
            float p3b = __shfl_sync(0xffffffffu, C[kt][3], srcB);
            float a[4];
            a[0] = tf32r((t & 1) ? p1a : p0a);
            a[1] = tf32r((t & 1) ? p3a : p2a);
            a[2] = tf32r((t & 1) ? p1b : p0b);
            a[3] = tf32r((t & 1) ? p3b : p2b);
#pragma unroll
            for (int nt = 0; nt < 8; nt++) {
                float b0 = Vb[(kt * 8 + t)     * VSTR + nt * 8 + g];
                float b1 = Vb[(kt * 8 + t + 4) * VSTR + nt * 8 + g];
                mma_tf32(O[nt], a, b0, b1);
            }
        }
        __syncthreads();   // all warps done with buf before it's overwritten next iter
    }

    // ---- coalesced fused epilogue: stage O in Ksm, then uint4 bf16 stores ----
    {
        float inv0 = 1.0f / l0, inv1 = 1.0f / l1;
#pragma unroll
        for (int nt = 0; nt < 8; nt++) {
            int col = nt * 8 + 2 * t;
            Ksm[(wm + g)     * STRD + col]     = O[nt][0] * inv0;
            Ksm[(wm + g)     * STRD + col + 1] = O[nt][1] * inv0;
            Ksm[(wm + g + 8) * STRD + col]     = O[nt][2] * inv1;
            Ksm[(wm + g + 8) * STRD + col + 1] = O[nt][3] * inv1;
        }
    }
    __syncthreads();

#pragma unroll
    for (int itr = 0; itr < 4; itr++) {
        int idx = itr * 256 + tid;
        int r  = idx >> 3;
        int c8 = (idx & 7) << 3;
        const float* s = Ksm + r * STRD + c8;
        uint32_t hw[4], lw[4];
#pragma unroll
        for (int j = 0; j < 4; j++) {
            float x0 = s[2 * j], x1 = s[2 * j + 1];
            __nv_bfloat16 h0 = __float2bfloat16(x0);
            __nv_bfloat16 h1 = __float2bfloat16(x1);
            __nv_bfloat16 e0 = __float2bfloat16(x0 - __bfloat162float(h0));
            __nv_bfloat16 e1 = __float2bfloat16(x1 - __bfloat162float(h1));
            hw[j] = pack_bf16(h0, h1);
            lw[j] = pack_bf16(e0, e1);
        }
        __nv_bfloat16* dst = Aout + (size_t)(b * NN + i0 + r) * KP + h * EE + c8;
        *(uint4*)(dst)          = *(uint4*)hw;
        *(uint4*)(dst + DD)     = *(uint4*)lw;
        *(uint4*)(dst + 2 * DD) = *(uint4*)hw;
    }
}

// ===========================================================================
extern "C" void kernel_launch(void* const* d_in, const int* in_sizes, int n_in,
                              void* d_out, int out_size) {
    const float* x    = (const float*)d_in[0];
    const float* Wqkv = (const float*)d_in[1];
    const float* Wo   = (const float*)d_in[2];
    float* out = (float*)d_out;

    float* qkv = nullptr;
    __nv_bfloat16* Abuf = nullptr;  __nv_bfloat16* Bbuf = nullptr;
    cudaGetSymbolAddress((void**)&qkv,  g_qkv);
    cudaGetSymbolAddress((void**)&Abuf, g_A);
    cudaGetSymbolAddress((void**)&Bbuf, g_B);

    cudaFuncSetAttribute(gemm_hmma, cudaFuncAttributeMaxDynamicSharedMemorySize, SMEM_GEMM);
    cudaFuncSetAttribute(attn_tc, cudaFuncAttributeMaxDynamicSharedMemorySize, SMEM_ATTN);

    // 1) x -> A' split
    split_rows<<<(MTOT * DD + 255) / 256, 256>>>(x, Abuf, MTOT);
    // 2) W_qkv -> B' split-transpose
    split_transpose<<<dim3(3 * DD / 32, DD / 32), dim3(32, 8)>>>(Wqkv, Bbuf, 3 * DD);
    // 3) QKV GEMM
    gemm_hmma<<<dim3(3 * DD / 128, MTOT / 128), 256, SMEM_GEMM>>>(Abuf, Bbuf, qkv, MTOT, 3 * DD);
    // 4) attention -> writes A' split directly
    attn_tc<<<dim3(NN / AT_I, BB * HH), 256, SMEM_ATTN>>>(qkv, Abuf);
    // 5) W_o -> B'
    split_transpose<<<dim3(DD / 32, DD / 32), dim3(32, 8)>>>(Wo, Bbuf, DD);
    // 6) O-proj GEMM
    gemm_hmma<<<dim3(DD / 128, MTOT / 128), 256, SMEM_GEMM>>>(Abuf, Bbuf, out, MTOT, DD);
}

// round 12
// speedup vs baseline: 1.5038x; 1.3077x over previous
#include <cuda_runtime.h>
#include <cuda_fp16.h>
#include <cuda_bf16.h>
#include <cstdint>
#include <math.h>

// ---------------------------------------------------------------------------
// Problem: x[4,2048,1024] f32; W_qkv[1024,3072]; W_o[1024,1024]; out[4,2048,1024]
//   1) split x -> A' fp16 [8192, 2048]  (hi | lo along K)
//   2) transpose W_qkv -> B' fp16 [3072, 1024] (hi only)
//   3) HMMA fp16 GEMM (K'=2048 vs B wrapped mod 1024) -> g_qkv
//   4) tf32 mma attention (R11 kernel) -> fused fp16 hi|lo split to A'
//   5) transpose W_o -> B'
//   6) HMMA fp16 GEMM -> out
// Error: C = A.fp16(B); residual ~2^-12 (1-sigma 1.4e-4) per GEMM.
// ---------------------------------------------------------------------------
#define BB 4
#define NN 2048
#define DD 1024
#define HH 16
#define EE 64
#define MTOT (BB * NN)   // 8192
#define KPA  2048        // A' row length (hi | lo)
#define KPB  1024        // B' row length (hi only)
#define SA   40          // gemm smem row stride in fp16 (32 data + 8 pad)
#define NSTAGE 64        // KPA / 32
#define PIPE 3

__device__ float  g_qkv[MTOT * 3 * DD];
__device__ __half g_A[MTOT * KPA];
__device__ __half g_B[3 * DD * KPB];

// ===========================================================================
__device__ __forceinline__ uint32_t smem_u32(const void* p) {
    uint32_t a;
    asm("{ .reg .u64 t; cvta.to.shared.u64 t, %1; cvt.u32.u64 %0, t; }"
        : "=r"(a) : "l"(p));
    return a;
}
__device__ __forceinline__ void cp_async16(uint32_t dst, const void* src) {
    asm volatile("cp.async.cg.shared.global [%0], [%1], 16;"
                 :: "r"(dst), "l"(src) : "memory");
}
__device__ __forceinline__ void ldsm_x4(uint32_t* r, uint32_t addr) {
    asm volatile("ldmatrix.sync.aligned.m8n8.x4.shared.b16 {%0,%1,%2,%3}, [%4];"
                 : "=r"(r[0]), "=r"(r[1]), "=r"(r[2]), "=r"(r[3]) : "r"(addr));
}
__device__ __forceinline__ void mma_f16(float* d, const uint32_t* a, const uint32_t* b) {
    asm volatile(
        "mma.sync.aligned.m16n8k16.row.col.f32.f16.f16.f32 "
        "{%0,%1,%2,%3}, {%4,%5,%6,%7}, {%8,%9}, {%0,%1,%2,%3};"
        : "+f"(d[0]), "+f"(d[1]), "+f"(d[2]), "+f"(d[3])
        : "r"(a[0]), "r"(a[1]), "r"(a[2]), "r"(a[3]), "r"(b[0]), "r"(b[1]));
}
__device__ __forceinline__ float tf32r(float x) {
    asm("cvt.rna.tf32.f32 %0, %0;" : "+f"(x));
    return x;
}
__device__ __forceinline__ void mma_tf32(float* d, const float* a, float b0f, float b1f) {
    uint32_t a0 = __float_as_uint(a[0]), a1 = __float_as_uint(a[1]);
    uint32_t a2 = __float_as_uint(a[2]), a3 = __float_as_uint(a[3]);
    uint32_t b0 = __float_as_uint(b0f), b1 = __float_as_uint(b1f);
    asm volatile(
        "mma.sync.aligned.m16n8k8.row.col.f32.tf32.tf32.f32 "
        "{%0,%1,%2,%3}, {%4,%5,%6,%7}, {%8,%9}, {%0,%1,%2,%3};"
        : "+f"(d[0]), "+f"(d[1]), "+f"(d[2]), "+f"(d[3])
        : "r"(a0), "r"(a1), "r"(a2), "r"(a3), "r"(b0), "r"(b1));
}
__device__ __forceinline__ uint32_t pack_h2(__half a, __half b) {
    __half2 p = __halves2half2(a, b);
    return *reinterpret_cast<uint32_t*>(&p);
}

// ===========================================================================
// HMMA fp16 GEMM: C[M,Nn] f32 = A'[M,2048] @ B'[Nn,1024]^T (B k wraps mod 1024)
// R4 shape: CTA 128x128, 8 warps of 64x32, BK=32, 3-stage cp.async ring.
// ===========================================================================
#define BUFB (128 * SA * 2)
#define SMEM_GEMM (PIPE * 2 * BUFB)

__global__ __launch_bounds__(256, 2)
void gemm_hmma(const __half* __restrict__ A,
               const __half* __restrict__ B,
               float* __restrict__ C, int M, int Nn) {
    extern __shared__ __half smhf[];
    const int tid  = threadIdx.x;
    const int wid  = tid >> 5;
    const int lane = tid & 31;
    const int m0 = blockIdx.y * 128;
    const int n0 = blockIdx.x * 128;
    const int wm = (wid >> 2) * 64;
    const int wn = (wid & 3) * 32;

    const uint32_t sbase = smem_u32(smhf);
    const uint32_t aoff0 = sbase;
    const uint32_t boff0 = sbase + PIPE * BUFB;

    const __half* Ag = A + (size_t)m0 * KPA;
    const __half* Bg = B + (size_t)n0 * KPB;

    const int lr  = tid >> 1;
    const int lkc = (tid & 1) * 2;

    auto load_stage = [&](int s) {
        const int buf = s % PIPE;
        const uint32_t ab = aoff0 + buf * BUFB;
        const uint32_t bb = boff0 + buf * BUFB;
        const int k0a = s * 32;
        const int k0b = (s & 31) * 32;     // wrap mod 1024
#pragma unroll
        for (int j = 0; j < 2; j++) {
            const int kc = lkc + j;
            const uint32_t doff = (uint32_t)(lr * SA + kc * 8) * 2;
            cp_async16(ab + doff, Ag + (size_t)lr * KPA + k0a + kc * 8);
            cp_async16(bb + doff, Bg + (size_t)lr * KPB + k0b + kc * 8);
        }
        asm volatile("cp.async.commit_group;" ::: "memory");
    };

    float acc[4][4][4];
#pragma unroll
    for (int i = 0; i < 4; i++)
#pragma unroll
        for (int j = 0; j < 4; j++)
#pragma unroll
            for (int k = 0; k < 4; k++) acc[i][j][k] = 0.0f;

    const int arow  = wm + (lane & 15);
    const int akoff = (lane >> 4) * 8;
    const int brow  = wn + (lane >> 4) * 8 + (lane & 7);
    const int bkoff = ((lane >> 3) & 1) * 8;

    load_stage(0);
    load_stage(1);

    for (int s = 0; s < NSTAGE; s++) {
        if (s + 1 < NSTAGE)
            asm volatile("cp.async.wait_group 1;" ::: "memory");
        else
            asm volatile("cp.async.wait_group 0;" ::: "memory");
        __syncthreads();
        if (s + 2 < NSTAGE) load_stage(s + 2);

        const int buf = s % PIPE;
        const uint32_t ab = aoff0 + buf * BUFB;
        const uint32_t bb = boff0 + buf * BUFB;

#pragma unroll
        for (int ksub = 0; ksub < 2; ksub++) {
            uint32_t af[4][4], bf[2][4];
#pragma unroll
            for (int mt = 0; mt < 4; mt++)
                ldsm_x4(af[mt], ab + (uint32_t)((arow + mt * 16) * SA + ksub * 16 + akoff) * 2);
#pragma unroll
            for (int p = 0; p < 2; p++)
                ldsm_x4(bf[p], bb + (uint32_t)((brow + p * 16) * SA + ksub * 16 + bkoff) * 2);
#pragma unroll
            for (int mt = 0; mt < 4; mt++) {
#pragma unroll
                for (int nt = 0; nt < 4; nt++)
                    mma_f16(acc[mt][nt], af[mt], &bf[nt >> 1][(nt & 1) * 2]);
            }
        }
    }

    const int grp = lane >> 2;
    const int tig = lane & 3;
#pragma unroll
    for (int mt = 0; mt < 4; mt++) {
#pragma unroll
        for (int nt = 0; nt < 4; nt++) {
            const int row = m0 + wm + mt * 16 + grp;
            const int col = n0 + wn + nt * 8 + tig * 2;
            float2 v0 = make_float2(acc[mt][nt][0], acc[mt][nt][1]);
            float2 v1 = make_float2(acc[mt][nt][2], acc[mt][nt][3]);
            *(float2*)&C[(size_t)row * Nn + col]       = v0;
            *(float2*)&C[(size_t)(row + 8) * Nn + col] = v1;
        }
    }
}

// ===========================================================================
// Conversion kernels (fp16 2-term split)
// ===========================================================================
__global__ __launch_bounds__(256)
void split_rows(const float* __restrict__ in, __half* __restrict__ out, int M) {
    int idx = blockIdx.x * 256 + threadIdx.x;
    if (idx >= M * DD) return;
    int m = idx >> 10, k = idx & 1023;
    float x = in[idx];
    __half hi = __float2half_rn(x);
    __half lo = __float2half_rn(x - __half2float(hi));
    __half* o = out + (size_t)m * KPA;
    o[k] = hi; o[DD + k] = lo;
}

__global__ __launch_bounds__(256)
void transpose_h(const float* __restrict__ W, __half* __restrict__ out, int Nw) {
    __shared__ float t[32][33];
    int n0 = blockIdx.x * 32, k0 = blockIdx.y * 32;
    int tx = threadIdx.x, ty = threadIdx.y;
#pragma unroll
    for (int i = ty; i < 32; i += 8)
        t[i][tx] = W[(size_t)(k0 + i) * Nw + n0 + tx];
    __syncthreads();
#pragma unroll
    for (int i = ty; i < 32; i += 8) {
        int n = n0 + i, k = k0 + tx;
        out[(size_t)n * KPB + k] = __float2half_rn(t[tx][i]);
    }
}

// ===========================================================================
// Attention — R11 kernel (313us), epilogue now writes fp16 hi|lo (2 regions)
// ===========================================================================
#define AT_I 128
#define AT_J 64
#define STRD 68
#define VSTR 72
#define QBUF (AT_J * STRD)
#define VBUF (AT_J * VSTR)
#define SMEM_ATTN ((AT_I * STRD + 2 * QBUF + 2 * VBUF) * (int)sizeof(float))

__global__ __launch_bounds__(256, 2)
void attn_tc(const float* __restrict__ qkv, __half* __restrict__ Aout) {
    extern __shared__ float sm[];
    float* Ksm = sm;
    float* Q2  = sm + AT_I * STRD;
    float* V2  = Q2 + 2 * QBUF;

    const uint32_t sbase = smem_u32(sm);
    const uint32_t q2off = sbase + (uint32_t)(AT_I * STRD) * 4;
    const uint32_t v2off = q2off + (uint32_t)(2 * QBUF) * 4;

    const int it = blockIdx.x;
    const int bh = blockIdx.y;
    const int b = bh >> 4, h = bh & 15;
    const int i0 = it * AT_I;

    const int tid  = threadIdx.x;
    const int wid  = tid >> 5;
    const int lane = tid & 31;
    const int g = lane >> 2;
    const int t = lane & 3;
    const int wm = wid * 16;

    const size_t RS = 3 * DD;
    const float* Qg = qkv + h * EE;
    const float* Kg = qkv + DD + h * EE;
    const float* Vg = qkv + 2 * DD + h * EE;

    const int jt0 = it * 2;
    const int nJT = NN / AT_J;

    auto prefetch_qv = [&](int jt, int buf) {
        const int j0 = jt * AT_J;
#pragma unroll
        for (int i = 0; i < 4; i++) {
            int idx = i * 256 + tid;
            int r = idx >> 4;
            int c = idx & 15;
            const float* qsrc = Qg + (size_t)(b * NN + j0 + r) * RS + c * 4;
            const float* vsrc = Vg + (size_t)(b * NN + j0 + r) * RS + c * 4;
            cp_async16(q2off + (uint32_t)(buf * QBUF + r * STRD) * 4 + c * 16, qsrc);
            cp_async16(v2off + (uint32_t)(buf * VBUF + r * VSTR) * 4 + c * 16, vsrc);
        }
        asm volatile("cp.async.commit_group;" ::: "memory");
    };

    prefetch_qv(jt0, 0);

#pragma unroll
    for (int q = 0; q < 8; q++) {
        int idx = q * 256 + tid;
        int r = idx >> 4, ec = (idx & 15) << 2;
        float4 v = *(const float4*)(Kg + (size_t)(b * NN + i0 + r) * RS + ec);
        float* d = Ksm + r * STRD + ec;
        d[0] = tf32r(v.x); d[1] = tf32r(v.y); d[2] = tf32r(v.z); d[3] = tf32r(v.w);
    }

    float m0 = -1e30f, m1 = -1e30f, l0 = 0.0f, l1 = 0.0f;
    float O[8][4];
#pragma unroll
    for (int nt = 0; nt < 8; nt++)
#pragma unroll
        for (int k = 0; k < 4; k++) O[nt][k] = 0.0f;

    const int r0g = i0 + wm + g;
    const int r1g = r0g + 8;

    for (int jt = jt0; jt < nJT; jt++) {
        const int j0 = jt * AT_J;
        const int buf = (jt - jt0) & 1;

        asm volatile("cp.async.wait_group 0;" ::: "memory");
        __syncthreads();
        if (jt + 1 < nJT) prefetch_qv(jt + 1, buf ^ 1);

        const float* Qb = Q2 + buf * QBUF;
        const float* Vb = V2 + buf * VBUF;

        float C[8][4];
#pragma unroll
        for (int nt = 0; nt < 8; nt++)
#pragma unroll
            for (int k = 0; k < 4; k++) C[nt][k] = 0.0f;

#pragma unroll
        for (int kt = 0; kt < 8; kt++) {
            float a[4];
            a[0] = Ksm[(wm + g)     * STRD + kt * 8 + t];
            a[1] = Ksm[(wm + g + 8) * STRD + kt * 8 + t];
            a[2] = Ksm[(wm + g)     * STRD + kt * 8 + t + 4];
            a[3] = Ksm[(wm + g + 8) * STRD + kt * 8 + t + 4];
#pragma unroll
            for (int nt = 0; nt < 8; nt++) {
                float b0 = Qb[(nt * 8 + g) * STRD + kt * 8 + t];
                float b1 = Qb[(nt * 8 + g) * STRD + kt * 8 + t + 4];
                mma_tf32(C[nt], a, b0, b1);
            }
        }

        const bool needmask = (j0 < i0 + AT_I);
        float rmax0 = -1e30f, rmax1 = -1e30f;
#pragma unroll
        for (int nt = 0; nt < 8; nt++) {
            C[nt][0] *= 0.125f; C[nt][1] *= 0.125f;
            C[nt][2] *= 0.125f; C[nt][3] *= 0.125f;
            if (needmask) {
                int c0 = j0 + nt * 8 + 2 * t;
                int c1 = c0 + 1;
                if (c0 < r0g) C[nt][0] = -1e30f;
                if (c1 < r0g) C[nt][1] = -1e30f;
                if (c0 < r1g) C[nt][2] = -1e30f;
                if (c1 < r1g) C[nt][3] = -1e30f;
            }
            rmax0 = fmaxf(rmax0, fmaxf(C[nt][0], C[nt][1]));
            rmax1 = fmaxf(rmax1, fmaxf(C[nt][2], C[nt][3]));
        }
        rmax0 = fmaxf(rmax0, __shfl_xor_sync(0xffffffffu, rmax0, 1));
        rmax0 = fmaxf(rmax0, __shfl_xor_sync(0xffffffffu, rmax0, 2));
        rmax1 = fmaxf(rmax1, __shfl_xor_sync(0xffffffffu, rmax1, 1));
        rmax1 = fmaxf(rmax1, __shfl_xor_sync(0xffffffffu, rmax1, 2));

        float mn0 = fmaxf(m0, rmax0), mn1 = fmaxf(m1, rmax1);
        float sc0 = __expf(m0 - mn0), sc1 = __expf(m1 - mn1);
        m0 = mn0; m1 = mn1;

        float rs0 = 0.0f, rs1 = 0.0f;
#pragma unroll
        for (int nt = 0; nt < 8; nt++) {
            C[nt][0] = __expf(C[nt][0] - mn0);
            C[nt][1] = __expf(C[nt][1] - mn0);
            C[nt][2] = __expf(C[nt][2] - mn1);
            C[nt][3] = __expf(C[nt][3] - mn1);
            rs0 += C[nt][0] + C[nt][1];
            rs1 += C[nt][2] + C[nt][3];
        }
        rs0 += __shfl_xor_sync(0xffffffffu, rs0, 1);
        rs0 += __shfl_xor_sync(0xffffffffu, rs0, 2);
        rs1 += __shfl_xor_sync(0xffffffffu, rs1, 1);
        rs1 += __shfl_xor_sync(0xffffffffu, rs1, 2);
        l0 = l0 * sc0 + rs0;
        l1 = l1 * sc1 + rs1;
#pragma unroll
        for (int nt = 0; nt < 8; nt++) {
            O[nt][0] *= sc0; O[nt][1] *= sc0;
            O[nt][2] *= sc1; O[nt][3] *= sc1;
        }

        const uint32_t srcA = (lane & 28) | (t >> 1);
        const uint32_t srcB = srcA + 2;
#pragma unroll
        for (int kt = 0; kt < 8; kt++) {
            float p0a = __shfl_sync(0xffffffffu, C[kt][0], srcA);
            float p1a = __shfl_sync(0xffffffffu, C[kt][1], srcA);
            float p2a = __shfl_sync(0xffffffffu, C[kt][2], srcA);
            float p3a = __shfl_sync(0xffffffffu, C[kt][3], srcA);
            float p0b = __shfl_sync(0xffffffffu, C[kt][0], srcB);
            float p1b = __shfl_sync(0xffffffffu, C[kt][1], srcB);
            float p2b = __shfl_sync(0xffffffffu, C[kt][2], srcB);
            float p3b = __shfl_sync(0xffffffffu, C[kt][3], srcB);
            float a[4];
            a[0] = tf32r((t & 1) ? p1a : p0a);
            a[1] = tf32r((t & 1) ? p3a : p2a);
            a[2] = tf32r((t & 1) ? p1b : p0b);
            a[3] = tf32r((t & 1) ? p3b : p2b);
#pragma unroll
            for (int nt = 0; nt < 8; nt++) {
                float b0 = Vb[(kt * 8 + t)     * VSTR + nt * 8 + g];
                float b1 = Vb[(kt * 8 + t + 4) * VSTR + nt * 8 + g];
                mma_tf32(O[nt], a, b0, b1);
            }
        }
        __syncthreads();
    }

    // ---- coalesced fused epilogue: stage O in Ksm, then uint4 fp16 stores ----
    {
        float inv0 = 1.0f / l0, inv1 = 1.0f / l1;
#pragma unroll
        for (int nt = 0; nt < 8; nt++) {
            int col = nt * 8 + 2 * t;
            Ksm[(wm + g)     * STRD + col]     = O[nt][0] * inv0;
            Ksm[(wm + g)     * STRD + col + 1] = O[nt][1] * inv0;
            Ksm[(wm + g + 8) * STRD + col]     = O[nt][2] * inv1;
            Ksm[(wm + g + 8) * STRD + col + 1] = O[nt][3] * inv1;
        }
    }
    __syncthreads();

#pragma unroll
    for (int itr = 0; itr < 4; itr++) {
        int idx = itr * 256 + tid;
        int r  = idx >> 3;
        int c8 = (idx & 7) << 3;
        const float* s = Ksm + r * STRD + c8;
        uint32_t hw[4], lw[4];
#pragma unroll
        for (int j = 0; j < 4; j++) {
            float x0 = s[2 * j], x1 = s[2 * j + 1];
            __half h0 = __float2half_rn(x0);
            __half h1 = __float2half_rn(x1);
            __half e0 = __float2half_rn(x0 - __half2float(h0));
            __half e1 = __float2half_rn(x1 - __half2float(h1));
            hw[j] = pack_h2(h0, h1);
            lw[j] = pack_h2(e0, e1);
        }
        __half* dst = Aout + (size_t)(b * NN + i0 + r) * KPA + h * EE + c8;
        *(uint4*)(dst)      = *(uint4*)hw;
        *(uint4*)(dst + DD) = *(uint4*)lw;
    }
}

// ===========================================================================
extern "C" void kernel_launch(void* const* d_in, const int* in_sizes, int n_in,
                              void* d_out, int out_size) {
    const float* x    = (const float*)d_in[0];
    const float* Wqkv = (const float*)d_in[1];
    const float* Wo   = (const float*)d_in[2];
    float* out = (float*)d_out;

    float* qkv = nullptr;
    __half* Abuf = nullptr;  __half* Bbuf = nullptr;
    cudaGetSymbolAddress((void**)&qkv,  g_qkv);
    cudaGetSymbolAddress((void**)&Abuf, g_A);
    cudaGetSymbolAddress((void**)&Bbuf, g_B);

    cudaFuncSetAttribute(gemm_hmma, cudaFuncAttributeMaxDynamicSharedMemorySize, SMEM_GEMM);
    cudaFuncSetAttribute(attn_tc, cudaFuncAttributeMaxDynamicSharedMemorySize, SMEM_ATTN);

    // 1) x -> A' fp16 hi|lo split
    split_rows<<<(MTOT * DD + 255) / 256, 256>>>(x, Abuf, MTOT);
    // 2) W_qkv -> B' fp16 transpose (hi only)
    transpose_h<<<dim3(3 * DD / 32, DD / 32), dim3(32, 8)>>>(Wqkv, Bbuf, 3 * DD);
    // 3) QKV GEMM
    gemm_hmma<<<dim3(3 * DD / 128, MTOT / 128), 256, SMEM_GEMM>>>(Abuf, Bbuf, qkv, MTOT, 3 * DD);
    // 4) attention -> writes A' fp16 split directly
    attn_tc<<<dim3(NN / AT_I, BB * HH), 256, SMEM_ATTN>>>(qkv, Abuf);
    // 5) W_o -> B'
    transpose_h<<<dim3(DD / 32, DD / 32), dim3(32, 8)>>>(Wo, Bbuf, DD);
    // 6) O-proj GEMM
    gemm_hmma<<<dim3(DD / 128, MTOT / 128), 256, SMEM_GEMM>>>(Abuf, Bbuf, out, MTOT, DD);
}

// round 13
// speedup vs baseline: 2.1057x; 1.4002x over previous
#include <cuda_runtime.h>
#include <cuda_fp16.h>
#include <cstdint>
#include <math.h>

// ---------------------------------------------------------------------------
// Problem: x[4,2048,1024] f32; W_qkv[1024,3072]; W_o[1024,1024]; out[4,2048,1024]
//   1) convert x -> A' fp16 [8192, 1024]
//   2) transpose W_qkv -> B' fp16 [3072, 1024]
//   3) HMMA fp16 GEMM (K=1024) -> g_qkv f32
//   4) tf32 mma attention (R11 kernel) -> fused fp16 convert to A'
//   5) transpose W_o -> B'
//   6) HMMA fp16 GEMM -> out
// Error: both operands fp16 (2^-12 1-sigma each per GEMM) + tf32 attention.
// ---------------------------------------------------------------------------
#define BB 4
#define NN 2048
#define DD 1024
#define HH 16
#define EE 64
#define MTOT (BB * NN)   // 8192
#define KPA  1024
#define KPB  1024
#define SA   40          // gemm smem row stride in fp16 (32 data + 8 pad)
#define NSTAGE 32        // KPA / 32
#define PIPE 3

__device__ float  g_qkv[MTOT * 3 * DD];
__device__ __half g_A[MTOT * KPA];
__device__ __half g_B[3 * DD * KPB];

// ===========================================================================
__device__ __forceinline__ uint32_t smem_u32(const void* p) {
    uint32_t a;
    asm("{ .reg .u64 t; cvta.to.shared.u64 t, %1; cvt.u32.u64 %0, t; }"
        : "=r"(a) : "l"(p));
    return a;
}
__device__ __forceinline__ void cp_async16(uint32_t dst, const void* src) {
    asm volatile("cp.async.cg.shared.global [%0], [%1], 16;"
                 :: "r"(dst), "l"(src) : "memory");
}
__device__ __forceinline__ void ldsm_x4(uint32_t* r, uint32_t addr) {
    asm volatile("ldmatrix.sync.aligned.m8n8.x4.shared.b16 {%0,%1,%2,%3}, [%4];"
                 : "=r"(r[0]), "=r"(r[1]), "=r"(r[2]), "=r"(r[3]) : "r"(addr));
}
__device__ __forceinline__ void mma_f16(float* d, const uint32_t* a, const uint32_t* b) {
    asm volatile(
        "mma.sync.aligned.m16n8k16.row.col.f32.f16.f16.f32 "
        "{%0,%1,%2,%3}, {%4,%5,%6,%7}, {%8,%9}, {%0,%1,%2,%3};"
        : "+f"(d[0]), "+f"(d[1]), "+f"(d[2]), "+f"(d[3])
        : "r"(a[0]), "r"(a[1]), "r"(a[2]), "r"(a[3]), "r"(b[0]), "r"(b[1]));
}
__device__ __forceinline__ float tf32r(float x) {
    asm("cvt.rna.tf32.f32 %0, %0;" : "+f"(x));
    return x;
}
__device__ __forceinline__ void mma_tf32(float* d, const float* a, float b0f, float b1f) {
    uint32_t a0 = __float_as_uint(a[0]), a1 = __float_as_uint(a[1]);
    uint32_t a2 = __float_as_uint(a[2]), a3 = __float_as_uint(a[3]);
    uint32_t b0 = __float_as_uint(b0f), b1 = __float_as_uint(b1f);
    asm volatile(
        "mma.sync.aligned.m16n8k8.row.col.f32.tf32.tf32.f32 "
        "{%0,%1,%2,%3}, {%4,%5,%6,%7}, {%8,%9}, {%0,%1,%2,%3};"
        : "+f"(d[0]), "+f"(d[1]), "+f"(d[2]), "+f"(d[3])
        : "r"(a0), "r"(a1), "r"(a2), "r"(a3), "r"(b0), "r"(b1));
}
__device__ __forceinline__ uint32_t pack_h2(__half a, __half b) {
    __half2 p = __halves2half2(a, b);
    return *reinterpret_cast<uint32_t*>(&p);
}

// ===========================================================================
// HMMA fp16 GEMM: C[M,Nn] f32 = A'[M,1024] @ B'[Nn,1024]^T
// R4 shape: CTA 128x128, 8 warps of 64x32, BK=32, 3-stage cp.async ring.
// ===========================================================================
#define BUFB (128 * SA * 2)
#define SMEM_GEMM (PIPE * 2 * BUFB)

__global__ __launch_bounds__(256, 2)
void gemm_hmma(const __half* __restrict__ A,
               const __half* __restrict__ B,
               float* __restrict__ C, int M, int Nn) {
    extern __shared__ __half smhf[];
    const int tid  = threadIdx.x;
    const int wid  = tid >> 5;
    const int lane = tid & 31;
    const int m0 = blockIdx.y * 128;
    const int n0 = blockIdx.x * 128;
    const int wm = (wid >> 2) * 64;
    const int wn = (wid & 3) * 32;

    const uint32_t sbase = smem_u32(smhf);
    const uint32_t aoff0 = sbase;
    const uint32_t boff0 = sbase + PIPE * BUFB;

    const __half* Ag = A + (size_t)m0 * KPA;
    const __half* Bg = B + (size_t)n0 * KPB;

    const int lr  = tid >> 1;
    const int lkc = (tid & 1) * 2;

    auto load_stage = [&](int s) {
        const int buf = s % PIPE;
        const uint32_t ab = aoff0 + buf * BUFB;
        const uint32_t bb = boff0 + buf * BUFB;
        const int k0 = s * 32;
#pragma unroll
        for (int j = 0; j < 2; j++) {
            const int kc = lkc + j;
            const uint32_t doff = (uint32_t)(lr * SA + kc * 8) * 2;
            cp_async16(ab + doff, Ag + (size_t)lr * KPA + k0 + kc * 8);
            cp_async16(bb + doff, Bg + (size_t)lr * KPB + k0 + kc * 8);
        }
        asm volatile("cp.async.commit_group;" ::: "memory");
    };

    float acc[4][4][4];
#pragma unroll
    for (int i = 0; i < 4; i++)
#pragma unroll
        for (int j = 0; j < 4; j++)
#pragma unroll
            for (int k = 0; k < 4; k++) acc[i][j][k] = 0.0f;

    const int arow  = wm + (lane & 15);
    const int akoff = (lane >> 4) * 8;
    const int brow  = wn + (lane >> 4) * 8 + (lane & 7);
    const int bkoff = ((lane >> 3) & 1) * 8;

    load_stage(0);
    load_stage(1);

    for (int s = 0; s < NSTAGE; s++) {
        if (s + 1 < NSTAGE)
            asm volatile("cp.async.wait_group 1;" ::: "memory");
        else
            asm volatile("cp.async.wait_group 0;" ::: "memory");
        __syncthreads();
        if (s + 2 < NSTAGE) load_stage(s + 2);

        const int buf = s % PIPE;
        const uint32_t ab = aoff0 + buf * BUFB;
        const uint32_t bb = boff0 + buf * BUFB;

#pragma unroll
        for (int ksub = 0; ksub < 2; ksub++) {
            uint32_t af[4][4], bf[2][4];
#pragma unroll
            for (int mt = 0; mt < 4; mt++)
                ldsm_x4(af[mt], ab + (uint32_t)((arow + mt * 16) * SA + ksub * 16 + akoff) * 2);
#pragma unroll
            for (int p = 0; p < 2; p++)
                ldsm_x4(bf[p], bb + (uint32_t)((brow + p * 16) * SA + ksub * 16 + bkoff) * 2);
#pragma unroll
            for (int mt = 0; mt < 4; mt++) {
#pragma unroll
                for (int nt = 0; nt < 4; nt++)
                    mma_f16(acc[mt][nt], af[mt], &bf[nt >> 1][(nt & 1) * 2]);
            }
        }
    }

    const int grp = lane >> 2;
    const int tig = lane & 3;
#pragma unroll
    for (int mt = 0; mt < 4; mt++) {
#pragma unroll
        for (int nt = 0; nt < 4; nt++) {
            const int row = m0 + wm + mt * 16 + grp;
            const int col = n0 + wn + nt * 8 + tig * 2;
            float2 v0 = make_float2(acc[mt][nt][0], acc[mt][nt][1]);
            float2 v1 = make_float2(acc[mt][nt][2], acc[mt][nt][3]);
            *(float2*)&C[(size_t)row * Nn + col]       = v0;
            *(float2*)&C[(size_t)(row + 8) * Nn + col] = v1;
        }
    }
}

// ===========================================================================
// Conversion kernels (plain fp16)
// ===========================================================================
__global__ __launch_bounds__(256)
void convert_rows(const float* __restrict__ in, __half* __restrict__ out, int total) {
    int idx = blockIdx.x * 256 + threadIdx.x;
    if (idx >= total) return;
    out[idx] = __float2half_rn(in[idx]);
}

__global__ __launch_bounds__(256)
void transpose_h(const float* __restrict__ W, __half* __restrict__ out, int Nw) {
    __shared__ float t[32][33];
    int n0 = blockIdx.x * 32, k0 = blockIdx.y * 32;
    int tx = threadIdx.x, ty = threadIdx.y;
#pragma unroll
    for (int i = ty; i < 32; i += 8)
        t[i][tx] = W[(size_t)(k0 + i) * Nw + n0 + tx];
    __syncthreads();
#pragma unroll
    for (int i = ty; i < 32; i += 8) {
        int n = n0 + i, k = k0 + tx;
        out[(size_t)n * KPB + k] = __float2half_rn(t[tx][i]);
    }
}

// ===========================================================================
// Attention — R11 kernel (measured ~315us), epilogue writes plain fp16 A'
// ===========================================================================
#define AT_I 128
#define AT_J 64
#define STRD 68
#define VSTR 72
#define QBUF (AT_J * STRD)
#define VBUF (AT_J * VSTR)
#define SMEM_ATTN ((AT_I * STRD + 2 * QBUF + 2 * VBUF) * (int)sizeof(float))

__global__ __launch_bounds__(256, 2)
void attn_tc(const float* __restrict__ qkv, __half* __restrict__ Aout) {
    extern __shared__ float sm[];
    float* Ksm = sm;
    float* Q2  = sm + AT_I * STRD;
    float* V2  = Q2 + 2 * QBUF;

    const uint32_t sbase = smem_u32(sm);
    const uint32_t q2off = sbase + (uint32_t)(AT_I * STRD) * 4;
    const uint32_t v2off = q2off + (uint32_t)(2 * QBUF) * 4;

    const int it = blockIdx.x;
    const int bh = blockIdx.y;
    const int b = bh >> 4, h = bh & 15;
    const int i0 = it * AT_I;

    const int tid  = threadIdx.x;
    const int wid  = tid >> 5;
    const int lane = tid & 31;
    const int g = lane >> 2;
    const int t = lane & 3;
    const int wm = wid * 16;

    const size_t RS = 3 * DD;
    const float* Qg = qkv + h * EE;
    const float* Kg = qkv + DD + h * EE;
    const float* Vg = qkv + 2 * DD + h * EE;

    const int jt0 = it * 2;
    const int nJT = NN / AT_J;

    auto prefetch_qv = [&](int jt, int buf) {
        const int j0 = jt * AT_J;
#pragma unroll
        for (int i = 0; i < 4; i++) {
            int idx = i * 256 + tid;
            int r = idx >> 4;
            int c = idx & 15;
            const float* qsrc = Qg + (size_t)(b * NN + j0 + r) * RS + c * 4;
            const float* vsrc = Vg + (size_t)(b * NN + j0 + r) * RS + c * 4;
            cp_async16(q2off + (uint32_t)(buf * QBUF + r * STRD) * 4 + c * 16, qsrc);
            cp_async16(v2off + (uint32_t)(buf * VBUF + r * VSTR) * 4 + c * 16, vsrc);
        }
        asm volatile("cp.async.commit_group;" ::: "memory");
    };

    prefetch_qv(jt0, 0);

#pragma unroll
    for (int q = 0; q < 8; q++) {
        int idx = q * 256 + tid;
        int r = idx >> 4, ec = (idx & 15) << 2;
        float4 v = *(const float4*)(Kg + (size_t)(b * NN + i0 + r) * RS + ec);
        float* d = Ksm + r * STRD + ec;
        d[0] = tf32r(v.x); d[1] = tf32r(v.y); d[2] = tf32r(v.z); d[3] = tf32r(v.w);
    }

    float m0 = -1e30f, m1 = -1e30f, l0 = 0.0f, l1 = 0.0f;
    float O[8][4];
#pragma unroll
    for (int nt = 0; nt < 8; nt++)
#pragma unroll
        for (int k = 0; k < 4; k++) O[nt][k] = 0.0f;

    const int r0g = i0 + wm + g;
    const int r1g = r0g + 8;

    for (int jt = jt0; jt < nJT; jt++) {
        const int j0 = jt * AT_J;
        const int buf = (jt - jt0) & 1;

        asm volatile("cp.async.wait_group 0;" ::: "memory");
        __syncthreads();
        if (jt + 1 < nJT) prefetch_qv(jt + 1, buf ^ 1);

        const float* Qb = Q2 + buf * QBUF;
        const float* Vb = V2 + buf * VBUF;

        float C[8][4];
#pragma unroll
        for (int nt = 0; nt < 8; nt++)
#pragma unroll
            for (int k = 0; k < 4; k++) C[nt][k] = 0.0f;

#pragma unroll
        for (int kt = 0; kt < 8; kt++) {
            float a[4];
            a[0] = Ksm[(wm + g)     * STRD + kt * 8 + t];
            a[1] = Ksm[(wm + g + 8) * STRD + kt * 8 + t];
            a[2] = Ksm[(wm + g)     * STRD + kt * 8 + t + 4];
            a[3] = Ksm[(wm + g + 8) * STRD + kt * 8 + t + 4];
#pragma unroll
            for (int nt = 0; nt < 8; nt++) {
                float b0 = Qb[(nt * 8 + g) * STRD + kt * 8 + t];
                float b1 = Qb[(nt * 8 + g) * STRD + kt * 8 + t + 4];
                mma_tf32(C[nt], a, b0, b1);
            }
        }

        const bool needmask = (j0 < i0 + AT_I);
        float rmax0 = -1e30f, rmax1 = -1e30f;
#pragma unroll
        for (int nt = 0; nt < 8; nt++) {
            C[nt][0] *= 0.125f; C[nt][1] *= 0.125f;
            C[nt][2] *= 0.125f; C[nt][3] *= 0.125f;
            if (needmask) {
                int c0 = j0 + nt * 8 + 2 * t;
                int c1 = c0 + 1;
                if (c0 < r0g) C[nt][0] = -1e30f;
                if (c1 < r0g) C[nt][1] = -1e30f;
                if (c0 < r1g) C[nt][2] = -1e30f;
                if (c1 < r1g) C[nt][3] = -1e30f;
            }
            rmax0 = fmaxf(rmax0, fmaxf(C[nt][0], C[nt][1]));
            rmax1 = fmaxf(rmax1, fmaxf(C[nt][2], C[nt][3]));
        }
        rmax0 = fmaxf(rmax0, __shfl_xor_sync(0xffffffffu, rmax0, 1));
        rmax0 = fmaxf(rmax0, __shfl_xor_sync(0xffffffffu, rmax0, 2));
        rmax1 = fmaxf(rmax1, __shfl_xor_sync(0xffffffffu, rmax1, 1));
        rmax1 = fmaxf(rmax1, __shfl_xor_sync(0xffffffffu, rmax1, 2));

        float mn0 = fmaxf(m0, rmax0), mn1 = fmaxf(m1, rmax1);
        float sc0 = __expf(m0 - mn0), sc1 = __expf(m1 - mn1);
        m0 = mn0; m1 = mn1;

        float rs0 = 0.0f, rs1 = 0.0f;
#pragma unroll
        for (int nt = 0; nt < 8; nt++) {
            C[nt][0] = __expf(C[nt][0] - mn0);
            C[nt][1] = __expf(C[nt][1] - mn0);
            C[nt][2] = __expf(C[nt][2] - mn1);
            C[nt][3] = __expf(C[nt][3] - mn1);
            rs0 += C[nt][0] + C[nt][1];
            rs1 += C[nt][2] + C[nt][3];
        }
        rs0 += __shfl_xor_sync(0xffffffffu, rs0, 1);
        rs0 += __shfl_xor_sync(0xffffffffu, rs0, 2);
        rs1 += __shfl_xor_sync(0xffffffffu, rs1, 1);
        rs1 += __shfl_xor_sync(0xffffffffu, rs1, 2);
        l0 = l0 * sc0 + rs0;
        l1 = l1 * sc1 + rs1;
#pragma unroll
        for (int nt = 0; nt < 8; nt++) {
            O[nt][0] *= sc0; O[nt][1] *= sc0;
            O[nt][2] *= sc1; O[nt][3] *= sc1;
        }

        const uint32_t srcA = (lane & 28) | (t >> 1);
        const uint32_t srcB = srcA + 2;
#pragma unroll
        for (int kt = 0; kt < 8; kt++) {
            float p0a = __shfl_sync(0xffffffffu, C[kt][0], srcA);
            float p1a = __shfl_sync(0xffffffffu, C[kt][1], srcA);
            float p2a = __shfl_sync(0xffffffffu, C[kt][2], srcA);
            float p3a = __shfl_sync(0xffffffffu, C[kt][3], srcA);
            float p0b = __shfl_sync(0xffffffffu, C[kt][0], srcB);
            float p1b = __shfl_sync(0xffffffffu, C[kt][1], srcB);
            float p2b = __shfl_sync(0xffffffffu, C[kt][2], srcB);
            float p3b = __shfl_sync(0xffffffffu, C[kt][3], srcB);
            float a[4];
            a[0] = tf32r((t & 1) ? p1a : p0a);
            a[1] = tf32r((t & 1) ? p3a : p2a);
            a[2] = tf32r((t & 1) ? p1b : p0b);
            a[3] = tf32r((t & 1) ? p3b : p2b);
#pragma unroll
            for (int nt = 0; nt < 8; nt++) {
                float b0 = Vb[(kt * 8 + t)     * VSTR + nt * 8 + g];
                float b1 = Vb[(kt * 8 + t + 4) * VSTR + nt * 8 + g];
                mma_tf32(O[nt], a, b0, b1);
            }
        }
        __syncthreads();
    }

    // ---- coalesced fused epilogue: stage O in Ksm, then uint4 fp16 stores ----
    {
        float inv0 = 1.0f / l0, inv1 = 1.0f / l1;
#pragma unroll
        for (int nt = 0; nt < 8; nt++) {
            int col = nt * 8 + 2 * t;
            Ksm[(wm + g)     * STRD + col]     = O[nt][0] * inv0;
            Ksm[(wm + g)     * STRD + col + 1] = O[nt][1] * inv0;
            Ksm[(wm + g + 8) * STRD + col]     = O[nt][2] * inv1;
            Ksm[(wm + g + 8) * STRD + col + 1] = O[nt][3] * inv1;
        }
    }
    __syncthreads();

#pragma unroll
    for (int itr = 0; itr < 4; itr++) {
        int idx = itr * 256 + tid;
        int r  = idx >> 3;
        int c8 = (idx & 7) << 3;
        const float* s = Ksm + r * STRD + c8;
        uint32_t hw[4];
#pragma unroll
        for (int j = 0; j < 4; j++) {
            __half h0 = __float2half_rn(s[2 * j]);
            __half h1 = __float2half_rn(s[2 * j + 1]);
            hw[j] = pack_h2(h0, h1);
        }
        __half* dst = Aout + (size_t)(b * NN + i0 + r) * KPA + h * EE + c8;
        *(uint4*)(dst) = *(uint4*)hw;
    }
}

// ===========================================================================
extern "C" void kernel_launch(void* const* d_in, const int* in_sizes, int n_in,
                              void* d_out, int out_size) {
    const float* x    = (const float*)d_in[0];
    const float* Wqkv = (const float*)d_in[1];
    const float* Wo   = (const float*)d_in[2];
    float* out = (float*)d_out;

    float* qkv = nullptr;
    __half* Abuf = nullptr;  __half* Bbuf = nullptr;
    cudaGetSymbolAddress((void**)&qkv,  g_qkv);
    cudaGetSymbolAddress((void**)&Abuf, g_A);
    cudaGetSymbolAddress((void**)&Bbuf, g_B);

    cudaFuncSetAttribute(gemm_hmma, cudaFuncAttributeMaxDynamicSharedMemorySize, SMEM_GEMM);
    cudaFuncSetAttribute(attn_tc, cudaFuncAttributeMaxDynamicSharedMemorySize, SMEM_ATTN);

    // 1) x -> A' fp16 convert
    convert_rows<<<(MTOT * DD + 255) / 256, 256>>>(x, Abuf, MTOT * DD);
    // 2) W_qkv -> B' fp16 transpose
    transpose_h<<<dim3(3 * DD / 32, DD / 32), dim3(32, 8)>>>(Wqkv, Bbuf, 3 * DD);
    // 3) QKV GEMM (K=1024)
    gemm_hmma<<<dim3(3 * DD / 128, MTOT / 128), 256, SMEM_GEMM>>>(Abuf, Bbuf, qkv, MTOT, 3 * DD);
    // 4) attention -> writes A' fp16 directly
    attn_tc<<<dim3(NN / AT_I, BB * HH), 256, SMEM_ATTN>>>(qkv, Abuf);
    // 5) W_o -> B'
    transpose_h<<<dim3(DD / 32, DD / 32), dim3(32, 8)>>>(Wo, Bbuf, DD);
    // 6) O-proj GEMM (K=1024)
    gemm_hmma<<<dim3(DD / 128, MTOT / 128), 256, SMEM_GEMM>>>(Abuf, Bbuf, out, MTOT, DD);
}

// round 14
// speedup vs baseline: 2.7842x; 1.3222x over previous
#include <cuda_runtime.h>
#include <cuda_fp16.h>
#include <cstdint>
#include <math.h>

// ---------------------------------------------------------------------------
// Problem: x[4,2048,1024] f32; W_qkv[1024,3072]; W_o[1024,1024]; out[4,2048,1024]
//   1) convert x -> A' fp16 [8192, 1024]
//   2) transpose W_qkv -> B' fp16 [3072, 1024]
//   3) HMMA fp16 GEMM (K=1024) -> g_qkv (fp16)
//   4) fp16 mma attention (ldmatrix frags, reg-direct P) -> fp16 A'
//   5) transpose W_o -> B'
//   6) HMMA fp16 GEMM -> out (f32)
// ---------------------------------------------------------------------------
#define BB 4
#define NN 2048
#define DD 1024
#define HH 16
#define EE 64
#define MTOT (BB * NN)   // 8192
#define KPA  1024
#define KPB  1024
#define SA   40          // gemm smem row stride in fp16 (32 data + 8 pad)
#define NSTAGE 32        // KPA / 32
#define PIPE 3

__device__ __half g_qkv[MTOT * 3 * DD];
__device__ __half g_A[MTOT * KPA];
__device__ __half g_B[3 * DD * KPB];

// ===========================================================================
__device__ __forceinline__ uint32_t smem_u32(const void* p) {
    uint32_t a;
    asm("{ .reg .u64 t; cvta.to.shared.u64 t, %1; cvt.u32.u64 %0, t; }"
        : "=r"(a) : "l"(p));
    return a;
}
__device__ __forceinline__ void cp_async16(uint32_t dst, const void* src) {
    asm volatile("cp.async.cg.shared.global [%0], [%1], 16;"
                 :: "r"(dst), "l"(src) : "memory");
}
__device__ __forceinline__ void ldsm_x4(uint32_t* r, uint32_t addr) {
    asm volatile("ldmatrix.sync.aligned.m8n8.x4.shared.b16 {%0,%1,%2,%3}, [%4];"
                 : "=r"(r[0]), "=r"(r[1]), "=r"(r[2]), "=r"(r[3]) : "r"(addr));
}
__device__ __forceinline__ void ldsm_x4_t(uint32_t* r, uint32_t addr) {
    asm volatile("ldmatrix.sync.aligned.m8n8.x4.trans.shared.b16 {%0,%1,%2,%3}, [%4];"
                 : "=r"(r[0]), "=r"(r[1]), "=r"(r[2]), "=r"(r[3]) : "r"(addr));
}
__device__ __forceinline__ void mma_f16(float* d, const uint32_t* a, const uint32_t* b) {
    asm volatile(
        "mma.sync.aligned.m16n8k16.row.col.f32.f16.f16.f32 "
        "{%0,%1,%2,%3}, {%4,%5,%6,%7}, {%8,%9}, {%0,%1,%2,%3};"
        : "+f"(d[0]), "+f"(d[1]), "+f"(d[2]), "+f"(d[3])
        : "r"(a[0]), "r"(a[1]), "r"(a[2]), "r"(a[3]), "r"(b[0]), "r"(b[1]));
}
__device__ __forceinline__ uint32_t f2h2(float lo, float hi) {
    __half2 p = __floats2half2_rn(lo, hi);
    return *reinterpret_cast<uint32_t*>(&p);
}

// ===========================================================================
// HMMA fp16 GEMM: C[M,Nn] = A'[M,1024] @ B'[Nn,1024]^T, OutT in {float,__half}
// R4 shape: CTA 128x128, 8 warps of 64x32, BK=32, 3-stage cp.async ring.
// ===========================================================================
#define BUFB (128 * SA * 2)
#define SMEM_GEMM (PIPE * 2 * BUFB)

template <typename OutT>
__global__ __launch_bounds__(256, 2)
void gemm_hmma(const __half* __restrict__ A,
               const __half* __restrict__ B,
               OutT* __restrict__ C, int M, int Nn) {
    extern __shared__ __half smhf[];
    const int tid  = threadIdx.x;
    const int wid  = tid >> 5;
    const int lane = tid & 31;
    const int m0 = blockIdx.y * 128;
    const int n0 = blockIdx.x * 128;
    const int wm = (wid >> 2) * 64;
    const int wn = (wid & 3) * 32;

    const uint32_t sbase = smem_u32(smhf);
    const uint32_t aoff0 = sbase;
    const uint32_t boff0 = sbase + PIPE * BUFB;

    const __half* Ag = A + (size_t)m0 * KPA;
    const __half* Bg = B + (size_t)n0 * KPB;

    const int lr  = tid >> 1;
    const int lkc = (tid & 1) * 2;

    auto load_stage = [&](int s) {
        const int buf = s % PIPE;
        const uint32_t ab = aoff0 + buf * BUFB;
        const uint32_t bb = boff0 + buf * BUFB;
        const int k0 = s * 32;
#pragma unroll
        for (int j = 0; j < 2; j++) {
            const int kc = lkc + j;
            const uint32_t doff = (uint32_t)(lr * SA + kc * 8) * 2;
            cp_async16(ab + doff, Ag + (size_t)lr * KPA + k0 + kc * 8);
            cp_async16(bb + doff, Bg + (size_t)lr * KPB + k0 + kc * 8);
        }
        asm volatile("cp.async.commit_group;" ::: "memory");
    };

    float acc[4][4][4];
#pragma unroll
    for (int i = 0; i < 4; i++)
#pragma unroll
        for (int j = 0; j < 4; j++)
#pragma unroll
            for (int k = 0; k < 4; k++) acc[i][j][k] = 0.0f;

    const int arow  = wm + (lane & 15);
    const int akoff = (lane >> 4) * 8;
    const int brow  = wn + (lane >> 4) * 8 + (lane & 7);
    const int bkoff = ((lane >> 3) & 1) * 8;

    load_stage(0);
    load_stage(1);

    for (int s = 0; s < NSTAGE; s++) {
        if (s + 1 < NSTAGE)
            asm volatile("cp.async.wait_group 1;" ::: "memory");
        else
            asm volatile("cp.async.wait_group 0;" ::: "memory");
        __syncthreads();
        if (s + 2 < NSTAGE) load_stage(s + 2);

        const int buf = s % PIPE;
        const uint32_t ab = aoff0 + buf * BUFB;
        const uint32_t bb = boff0 + buf * BUFB;

#pragma unroll
        for (int ksub = 0; ksub < 2; ksub++) {
            uint32_t af[4][4], bf[2][4];
#pragma unroll
            for (int mt = 0; mt < 4; mt++)
                ldsm_x4(af[mt], ab + (uint32_t)((arow + mt * 16) * SA + ksub * 16 + akoff) * 2);
#pragma unroll
            for (int p = 0; p < 2; p++)
                ldsm_x4(bf[p], bb + (uint32_t)((brow + p * 16) * SA + ksub * 16 + bkoff) * 2);
#pragma unroll
            for (int mt = 0; mt < 4; mt++) {
#pragma unroll
                for (int nt = 0; nt < 4; nt++)
                    mma_f16(acc[mt][nt], af[mt], &bf[nt >> 1][(nt & 1) * 2]);
            }
        }
    }

    const int grp = lane >> 2;
    const int tig = lane & 3;
#pragma unroll
    for (int mt = 0; mt < 4; mt++) {
#pragma unroll
        for (int nt = 0; nt < 4; nt++) {
            const int row = m0 + wm + mt * 16 + grp;
            const int col = n0 + wn + nt * 8 + tig * 2;
            if constexpr (sizeof(OutT) == 2) {
                uint32_t v0 = f2h2(acc[mt][nt][0], acc[mt][nt][1]);
                uint32_t v1 = f2h2(acc[mt][nt][2], acc[mt][nt][3]);
                *(uint32_t*)&C[(size_t)row * Nn + col]       = v0;
                *(uint32_t*)&C[(size_t)(row + 8) * Nn + col] = v1;
            } else {
                float2 v0 = make_float2(acc[mt][nt][0], acc[mt][nt][1]);
                float2 v1 = make_float2(acc[mt][nt][2], acc[mt][nt][3]);
                *(float2*)&C[(size_t)row * Nn + col]       = v0;
                *(float2*)&C[(size_t)(row + 8) * Nn + col] = v1;
            }
        }
    }
}

// ===========================================================================
// Conversion kernels
// ===========================================================================
__global__ __launch_bounds__(256)
void convert_rows(const float* __restrict__ in, __half* __restrict__ out, int total) {
    int idx = blockIdx.x * 256 + threadIdx.x;
    if (idx >= total) return;
    out[idx] = __float2half_rn(in[idx]);
}

__global__ __launch_bounds__(256)
void transpose_h(const float* __restrict__ W, __half* __restrict__ out, int Nw) {
    __shared__ float t[32][33];
    int n0 = blockIdx.x * 32, k0 = blockIdx.y * 32;
    int tx = threadIdx.x, ty = threadIdx.y;
#pragma unroll
    for (int i = ty; i < 32; i += 8)
        t[i][tx] = W[(size_t)(k0 + i) * Nw + n0 + tx];
    __syncthreads();
#pragma unroll
    for (int i = ty; i < 32; i += 8) {
        int n = n0 + i, k = k0 + tx;
        out[(size_t)n * KPB + k] = __float2half_rn(t[tx][i]);
    }
}

// ===========================================================================
// Attention, fp16 mma (m16n8k16), ldmatrix fragments, reg-direct P.
// CTA: 128 i-rows x (b,h); 8 warps of m16; j streamed 64-wide from diagonal.
// Smem tiles fp16 stride 72 halves (144B; 144/16=9 odd -> ldsm conflict-free).
// ===========================================================================
#define AT_I 128
#define AT_J 64
#define HSTR 72
#define KBUF (AT_I * HSTR)          // halves
#define QBUF (AT_J * HSTR)
#define VBUF (AT_J * HSTR)
#define SMEM_ATTN ((KBUF + 2 * QBUF + 2 * VBUF) * 2)

__global__ __launch_bounds__(256, 2)
void attn_tc(const __half* __restrict__ qkv, __half* __restrict__ Aout) {
    extern __shared__ __half smh[];
    __half* Ksm = smh;

    const uint32_t sbase = smem_u32(smh);
    const uint32_t koff  = sbase;
    const uint32_t q2off = sbase + (uint32_t)KBUF * 2;
    const uint32_t v2off = q2off + (uint32_t)(2 * QBUF) * 2;

    const int it = blockIdx.x;
    const int bh = blockIdx.y;
    const int b = bh >> 4, h = bh & 15;
    const int i0 = it * AT_I;

    const int tid  = threadIdx.x;
    const int wid  = tid >> 5;
    const int lane = tid & 31;
    const int g = lane >> 2;
    const int t = lane & 3;
    const int wm = wid * 16;

    const size_t RS = 3 * DD;     // qkv row stride in halves
    const __half* Qg = qkv + h * EE;
    const __half* Kg = qkv + DD + h * EE;
    const __half* Vg = qkv + 2 * DD + h * EE;

    const int jt0 = it * 2;
    const int nJT = NN / AT_J;

    // Q/V tile prefetch: 64 rows x 8 chunks of 8 halves each (512 chunks/tile)
    auto prefetch_qv = [&](int jt, int buf) {
        const int j0 = jt * AT_J;
#pragma unroll
        for (int i = 0; i < 2; i++) {
            int idx = i * 256 + tid;
            int r = idx >> 3;
            int c = idx & 7;
            const __half* qsrc = Qg + (size_t)(b * NN + j0 + r) * RS + c * 8;
            const __half* vsrc = Vg + (size_t)(b * NN + j0 + r) * RS + c * 8;
            cp_async16(q2off + (uint32_t)(buf * QBUF + r * HSTR + c * 8) * 2, qsrc);
            cp_async16(v2off + (uint32_t)(buf * VBUF + r * HSTR + c * 8) * 2, vsrc);
        }
        asm volatile("cp.async.commit_group;" ::: "memory");
    };

    prefetch_qv(jt0, 0);

    // K tile via cp.async: 128 rows x 8 chunks
#pragma unroll
    for (int i = 0; i < 4; i++) {
        int idx = i * 256 + tid;
        int r = idx >> 3;
        int c = idx & 7;
        cp_async16(koff + (uint32_t)(r * HSTR + c * 8) * 2,
                   Kg + (size_t)(b * NN + i0 + r) * RS + c * 8);
    }
    asm volatile("cp.async.commit_group;" ::: "memory");

    float m0 = -1e30f, m1 = -1e30f, l0 = 0.0f, l1 = 0.0f;
    float O[8][4];
#pragma unroll
    for (int nt = 0; nt < 8; nt++)
#pragma unroll
        for (int k = 0; k < 4; k++) O[nt][k] = 0.0f;

    const int r0g = i0 + wm + g;
    const int r1g = r0g + 8;

    // ldmatrix lane address components
    const int a_row  = wm + (lane & 15);          // K (A) rows
    const int a_koff = (lane >> 4) * 8;
    const int b_row  = (lane >> 4) * 8 + (lane & 7); // Q (B) rows (local)
    const int b_koff = ((lane >> 3) & 1) * 8;
    const int v_row  = lane & 15;                 // V trans rows (local j)
    const int v_eoff = (lane >> 4) * 8;

    for (int jt = jt0; jt < nJT; jt++) {
        const int j0 = jt * AT_J;
        const int buf = (jt - jt0) & 1;

        asm volatile("cp.async.wait_group 0;" ::: "memory");
        __syncthreads();
        if (jt + 1 < nJT) prefetch_qv(jt + 1, buf ^ 1);

        const uint32_t qb = q2off + (uint32_t)(buf * QBUF) * 2;
        const uint32_t vb = v2off + (uint32_t)(buf * VBUF) * 2;

        // ---- S = K_i . Q_j  (fp16 mma, k16 x 4) ----
        float C[8][4];
#pragma unroll
        for (int nt = 0; nt < 8; nt++)
#pragma unroll
            for (int k = 0; k < 4; k++) C[nt][k] = 0.0f;

#pragma unroll
        for (int kt = 0; kt < 4; kt++) {
            uint32_t af[4];
            ldsm_x4(af, koff + (uint32_t)(a_row * HSTR + kt * 16 + a_koff) * 2);
            uint32_t qf[4][4];
#pragma unroll
            for (int p = 0; p < 4; p++)
                ldsm_x4(qf[p], qb + (uint32_t)((p * 16 + b_row) * HSTR + kt * 16 + b_koff) * 2);
#pragma unroll
            for (int nt = 0; nt < 8; nt++)
                mma_f16(C[nt], af, &qf[nt >> 1][(nt & 1) * 2]);
        }

        // ---- scale + mask ----
        const bool needmask = (j0 < i0 + AT_I);
        float rmax0 = -1e30f, rmax1 = -1e30f;
#pragma unroll
        for (int nt = 0; nt < 8; nt++) {
            C[nt][0] *= 0.125f; C[nt][1] *= 0.125f;
            C[nt][2] *= 0.125f; C[nt][3] *= 0.125f;
            if (needmask) {
                int c0 = j0 + nt * 8 + 2 * t;
                int c1 = c0 + 1;
                if (c0 < r0g) C[nt][0] = -1e30f;
                if (c1 < r0g) C[nt][1] = -1e30f;
                if (c0 < r1g) C[nt][2] = -1e30f;
                if (c1 < r1g) C[nt][3] = -1e30f;
            }
            rmax0 = fmaxf(rmax0, fmaxf(C[nt][0], C[nt][1]));
            rmax1 = fmaxf(rmax1, fmaxf(C[nt][2], C[nt][3]));
        }
        rmax0 = fmaxf(rmax0, __shfl_xor_sync(0xffffffffu, rmax0, 1));
        rmax0 = fmaxf(rmax0, __shfl_xor_sync(0xffffffffu, rmax0, 2));
        rmax1 = fmaxf(rmax1, __shfl_xor_sync(0xffffffffu, rmax1, 1));
        rmax1 = fmaxf(rmax1, __shfl_xor_sync(0xffffffffu, rmax1, 2));

        float mn0 = fmaxf(m0, rmax0), mn1 = fmaxf(m1, rmax1);
        float sc0 = __expf(m0 - mn0), sc1 = __expf(m1 - mn1);
        m0 = mn0; m1 = mn1;

        float rs0 = 0.0f, rs1 = 0.0f;
#pragma unroll
        for (int nt = 0; nt < 8; nt++) {
            C[nt][0] = __expf(C[nt][0] - mn0);
            C[nt][1] = __expf(C[nt][1] - mn0);
            C[nt][2] = __expf(C[nt][2] - mn1);
            C[nt][3] = __expf(C[nt][3] - mn1);
            rs0 += C[nt][0] + C[nt][1];
            rs1 += C[nt][2] + C[nt][3];
        }
        rs0 += __shfl_xor_sync(0xffffffffu, rs0, 1);
        rs0 += __shfl_xor_sync(0xffffffffu, rs0, 2);
        rs1 += __shfl_xor_sync(0xffffffffu, rs1, 1);
        rs1 += __shfl_xor_sync(0xffffffffu, rs1, 2);
        l0 = l0 * sc0 + rs0;
        l1 = l1 * sc1 + rs1;
#pragma unroll
        for (int nt = 0; nt < 8; nt++) {
            O[nt][0] *= sc0; O[nt][1] *= sc0;
            O[nt][2] *= sc1; O[nt][3] *= sc1;
        }

        // ---- O += P @ V : P = C frags converted in-register (no shuffles);
        //      V fragments via ldmatrix.trans on row-major [j][e] tile ----
#pragma unroll
        for (int kt = 0; kt < 4; kt++) {
            uint32_t a[4];
            a[0] = f2h2(C[2 * kt][0],     C[2 * kt][1]);
            a[1] = f2h2(C[2 * kt][2],     C[2 * kt][3]);
            a[2] = f2h2(C[2 * kt + 1][0], C[2 * kt + 1][1]);
            a[3] = f2h2(C[2 * kt + 1][2], C[2 * kt + 1][3]);
#pragma unroll
            for (int e0 = 0; e0 < 64; e0 += 16) {
                uint32_t vf[4];
                ldsm_x4_t(vf, vb + (uint32_t)((kt * 16 + v_row) * HSTR + e0 + v_eoff) * 2);
                mma_f16(O[e0 >> 3],       a, &vf[0]);
                mma_f16(O[(e0 >> 3) + 1], a, &vf[2]);
            }
        }
        __syncthreads();
    }

    // ---- fused epilogue: stage fp16 O in Ksm, coalesced uint4 stores ----
    {
        float inv0 = 1.0f / l0, inv1 = 1.0f / l1;
#pragma unroll
        for (int nt = 0; nt < 8; nt++) {
            int col = nt * 8 + 2 * t;
            *(uint32_t*)&Ksm[(wm + g)     * HSTR + col] = f2h2(O[nt][0] * inv0, O[nt][1] * inv0);
            *(uint32_t*)&Ksm[(wm + g + 8) * HSTR + col] = f2h2(O[nt][2] * inv1, O[nt][3] * inv1);
        }
    }
    __syncthreads();

#pragma unroll
    for (int itr = 0; itr < 4; itr++) {
        int idx = itr * 256 + tid;        // 1024: 128 rows x 8 chunks of 8 halves
        int r  = idx >> 3;
        int c8 = (idx & 7) << 3;
        uint4 v = *(const uint4*)&Ksm[r * HSTR + c8];
        __half* dst = Aout + (size_t)(b * NN + i0 + r) * KPA + h * EE + c8;
        *(uint4*)dst = v;
    }
}

// ===========================================================================
extern "C" void kernel_launch(void* const* d_in, const int* in_sizes, int n_in,
                              void* d_out, int out_size) {
    const float* x    = (const float*)d_in[0];
    const float* Wqkv = (const float*)d_in[1];
    const float* Wo   = (const float*)d_in[2];
    float* out = (float*)d_out;

    __half* qkv = nullptr;
    __half* Abuf = nullptr;  __half* Bbuf = nullptr;
    cudaGetSymbolAddress((void**)&qkv,  g_qkv);
    cudaGetSymbolAddress((void**)&Abuf, g_A);
    cudaGetSymbolAddress((void**)&Bbuf, g_B);

    cudaFuncSetAttribute(gemm_hmma<__half>, cudaFuncAttributeMaxDynamicSharedMemorySize, SMEM_GEMM);
    cudaFuncSetAttribute(gemm_hmma<float>,  cudaFuncAttributeMaxDynamicSharedMemorySize, SMEM_GEMM);
    cudaFuncSetAttribute(attn_tc, cudaFuncAttributeMaxDynamicSharedMemorySize, SMEM_ATTN);

    // 1) x -> A' fp16
    convert_rows<<<(MTOT * DD + 255) / 256, 256>>>(x, Abuf, MTOT * DD);
    // 2) W_qkv -> B' fp16 transpose
    transpose_h<<<dim3(3 * DD / 32, DD / 32), dim3(32, 8)>>>(Wqkv, Bbuf, 3 * DD);
    // 3) QKV GEMM -> fp16 qkv
    gemm_hmma<__half><<<dim3(3 * DD / 128, MTOT / 128), 256, SMEM_GEMM>>>(Abuf, Bbuf, qkv, MTOT, 3 * DD);
    // 4) attention (fp16 mma) -> fp16 A'
    attn_tc<<<dim3(NN / AT_I, BB * HH), 256, SMEM_ATTN>>>(qkv, Abuf);
    // 5) W_o -> B'
    transpose_h<<<dim3(DD / 32, DD / 32), dim3(32, 8)>>>(Wo, Bbuf, DD);
    // 6) O-proj GEMM -> f32 out
    gemm_hmma<float><<<dim3(DD / 128, MTOT / 128), 256, SMEM_GEMM>>>(Abuf, Bbuf, out, MTOT, DD);
}